// round 5
// baseline (speedup 1.0000x reference)
#include <cuda_runtime.h>
#include <cuda_bf16.h>
#include <cstdint>

#define CM 1024
#define TT 2048
#define BB 4
#define HH 16
#define MR (BB*TT)   // 8192 rows

// ---------------------------------------------------------------------------
// Scratch (device globals: allocation-free per harness rules)
// ---------------------------------------------------------------------------
__device__ __nv_bfloat16 g_x_hi[(size_t)MR * CM],     g_x_lo[(size_t)MR * CM];
__device__ __nv_bfloat16 g_wqkv_hi[3 * CM * CM],      g_wqkv_lo[3 * CM * CM];
__device__ __nv_bfloat16 g_wout_hi[CM * CM],          g_wout_lo[CM * CM];
__device__ __nv_bfloat16 g_qkv_hi[(size_t)MR * 3 * CM], g_qkv_lo[(size_t)MR * 3 * CM];
__device__ __nv_bfloat16 g_att_hi[(size_t)MR * CM],   g_att_lo[(size_t)MR * CM];

// ---------------------------------------------------------------------------
// helpers
// ---------------------------------------------------------------------------
__device__ __forceinline__ uint32_t smem_u32(const void* p) {
  uint32_t a;
  asm("{ .reg .u64 t; cvta.to.shared.u64 t, %1; cvt.u32.u64 %0, t; }"
      : "=r"(a) : "l"(p));
  return a;
}
__device__ __forceinline__ void cp16(uint32_t s, const void* g) {
  asm volatile("cp.async.cg.shared.global [%0], [%1], 16;" :: "r"(s), "l"(g));
}
#define CP_COMMIT() asm volatile("cp.async.commit_group;" ::: "memory")
#define CP_WAIT(n)  asm volatile("cp.async.wait_group %0;" :: "n"(n) : "memory")

// D += A*B, m16n8k16 bf16, fp32 accumulate
__device__ __forceinline__ void mma16(float* d, const uint32_t* a,
                                      uint32_t b0, uint32_t b1) {
  asm volatile(
      "mma.sync.aligned.m16n8k16.row.col.f32.bf16.bf16.f32 "
      "{%0,%1,%2,%3}, {%4,%5,%6,%7}, {%8,%9}, {%0,%1,%2,%3};"
      : "+f"(d[0]), "+f"(d[1]), "+f"(d[2]), "+f"(d[3])
      : "r"(a[0]), "r"(a[1]), "r"(a[2]), "r"(a[3]), "r"(b0), "r"(b1));
}
__device__ __forceinline__ void ldsm4(uint32_t* r, uint32_t a) {
  asm volatile("ldmatrix.sync.aligned.m8n8.x4.shared.b16 {%0,%1,%2,%3}, [%4];"
               : "=r"(r[0]), "=r"(r[1]), "=r"(r[2]), "=r"(r[3]) : "r"(a));
}
__device__ __forceinline__ void ldsm4t(uint32_t* r, uint32_t a) {
  asm volatile("ldmatrix.sync.aligned.m8n8.x4.trans.shared.b16 {%0,%1,%2,%3}, [%4];"
               : "=r"(r[0]), "=r"(r[1]), "=r"(r[2]), "=r"(r[3]) : "r"(a));
}
__device__ __forceinline__ uint32_t sw128(uint32_t o) { return o ^ ((o >> 3) & 0x70); }

// split fp32 -> bf16 hi + bf16 lo (x = hi + lo + O(2^-18 x))
__device__ __forceinline__ void split1(float x, uint16_t& h, uint16_t& l) {
  __nv_bfloat16 bh = __float2bfloat16_rn(x);
  float r = x - __bfloat162float(bh);
  __nv_bfloat16 bl = __float2bfloat16_rn(r);
  h = __bfloat16_as_ushort(bh);
  l = __bfloat16_as_ushort(bl);
}

// ---------------------------------------------------------------------------
// elementwise split: fp32 -> (hi, lo) bf16
// ---------------------------------------------------------------------------
__global__ __launch_bounds__(256) void split_kernel(
    const float* __restrict__ in, __nv_bfloat16* __restrict__ hi,
    __nv_bfloat16* __restrict__ lo, int n4) {
  int i = blockIdx.x * blockDim.x + threadIdx.x;
  if (i >= n4) return;
  float4 v = ((const float4*)in)[i];
  uint16_t h0, h1, h2, h3, l0, l1, l2, l3;
  split1(v.x, h0, l0); split1(v.y, h1, l1);
  split1(v.z, h2, l2); split1(v.w, h3, l3);
  ((uint2*)hi)[i] = make_uint2(h0 | ((uint32_t)h1 << 16), h2 | ((uint32_t)h3 << 16));
  ((uint2*)lo)[i] = make_uint2(l0 | ((uint32_t)l1 << 16), l2 | ((uint32_t)l3 << 16));
}

// ---------------------------------------------------------------------------
// bf16x3 TN GEMM: C[M,N] = A[M,K] * B[N,K]^T, A/B given as bf16 hi/lo pairs.
// CTA 128x128, BK=64, 3-stage cp.async, 256 threads (8 warps: 2x4, 64x32 each)
// ldmatrix fragment loads, pass-major MMA issue (acc-reuse distance 16).
// MODE 0: write fp32 C.  MODE 1: write bf16 hi/lo C.
// ---------------------------------------------------------------------------
#define GSMEM_TOTAL (3 * 65536)

template<int MODE>
__global__ __launch_bounds__(256) void gemm3(
    const __nv_bfloat16* __restrict__ Ah_, const __nv_bfloat16* __restrict__ Al_,
    const __nv_bfloat16* __restrict__ Bh_, const __nv_bfloat16* __restrict__ Bl_,
    float* __restrict__ Cf, __nv_bfloat16* __restrict__ Chi,
    __nv_bfloat16* __restrict__ Clo, int N, int K) {
  extern __shared__ char sm[];
  const int tid = threadIdx.x, w = tid >> 5, lane = tid & 31;
  const int g = lane >> 2, t = lane & 3;
  const int wm = w & 1, wn = w >> 1;
  const int bm = blockIdx.y * 128, bn = blockIdx.x * 128;
  // ldmatrix lane geometry
  const int row16 = ((lane >> 3) & 1) * 8 + (lane & 7);
  const int khalf = lane >> 4;
  const uint32_t rx = (uint32_t)(lane & 7) << 4;

  float acc[4][4][4];
#pragma unroll
  for (int mt = 0; mt < 4; mt++)
#pragma unroll
    for (int nt = 0; nt < 4; nt++)
#pragma unroll
      for (int r = 0; r < 4; r++) acc[mt][nt][r] = 0.f;

  // stage: Ah | Al | Bh | Bl, each 128 rows x 128B (64 bf16), SW128 swizzled
  auto fill = [&](int s, int k0) {
    char* base = sm + s * 65536;
#pragma unroll
    for (int i = tid; i < 1024; i += 256) {
      int row = i >> 3, c = i & 7;
      uint32_t swo = sw128((uint32_t)(row * 128 + c * 16));
      size_t ao = (size_t)(bm + row) * K + k0 + c * 8;
      size_t bo = (size_t)(bn + row) * K + k0 + c * 8;
      cp16(smem_u32(base + swo),         Ah_ + ao);
      cp16(smem_u32(base + 16384 + swo), Al_ + ao);
      cp16(smem_u32(base + 32768 + swo), Bh_ + bo);
      cp16(smem_u32(base + 49152 + swo), Bl_ + bo);
    }
  };

  const int KT = K >> 6;
  fill(0, 0);   CP_COMMIT();
  fill(1, 64);  CP_COMMIT();
  fill(2, 128); CP_COMMIT();

  for (int c = 0; c < KT; c++) {
    const int s = c - (c / 3) * 3;
    CP_WAIT(2);
    __syncthreads();
    const uint32_t ahU = smem_u32(sm + s * 65536);
    const uint32_t alU = ahU + 16384;
    const uint32_t bhU = ahU + 32768;
    const uint32_t blU = ahU + 49152;
#pragma unroll
    for (int kt = 0; kt < 4; kt++) {
      const uint32_t colb = ((uint32_t)(kt * 32 + khalf * 16)) ^ rx;
      uint32_t ah[4][4], al[4][4], bf[4][2];
#pragma unroll
      for (int mt = 0; mt < 4; mt++) {
        const uint32_t rel = (uint32_t)((wm * 64 + mt * 16 + row16) * 128) + colb;
        ldsm4(ah[mt], ahU + rel);
        ldsm4(al[mt], alU + rel);
      }
#pragma unroll
      for (int ntp = 0; ntp < 2; ntp++) {
        uint32_t r[4];
        ldsm4(r, bhU + (uint32_t)((wn * 32 + ntp * 16 + row16) * 128) + colb);
        bf[2*ntp][0] = r[0]; bf[2*ntp+1][0] = r[1];
        bf[2*ntp][1] = r[2]; bf[2*ntp+1][1] = r[3];
      }
      // pass 1: Ah x Bh
#pragma unroll
      for (int nt = 0; nt < 4; nt++)
#pragma unroll
        for (int mt = 0; mt < 4; mt++)
          mma16(acc[mt][nt], ah[mt], bf[nt][0], bf[nt][1]);
      // pass 2: Al x Bh
#pragma unroll
      for (int nt = 0; nt < 4; nt++)
#pragma unroll
        for (int mt = 0; mt < 4; mt++)
          mma16(acc[mt][nt], al[mt], bf[nt][0], bf[nt][1]);
      // load Bl (Bh dead), pass 3: Ah x Bl
#pragma unroll
      for (int ntp = 0; ntp < 2; ntp++) {
        uint32_t r[4];
        ldsm4(r, blU + (uint32_t)((wn * 32 + ntp * 16 + row16) * 128) + colb);
        bf[2*ntp][0] = r[0]; bf[2*ntp+1][0] = r[1];
        bf[2*ntp][1] = r[2]; bf[2*ntp+1][1] = r[3];
      }
#pragma unroll
      for (int nt = 0; nt < 4; nt++)
#pragma unroll
        for (int mt = 0; mt < 4; mt++)
          mma16(acc[mt][nt], ah[mt], bf[nt][0], bf[nt][1]);
    }
    __syncthreads();
    if (c + 3 < KT) fill(s, (c + 3) * 64);
    CP_COMMIT();
  }

#pragma unroll
  for (int mt = 0; mt < 4; mt++) {
#pragma unroll
    for (int nt = 0; nt < 4; nt++) {
      const int row = bm + wm * 64 + mt * 16 + g;
      const int col = bn + wn * 32 + nt * 8 + 2 * t;
      if (MODE == 0) {
        *(float2*)(Cf + (size_t)row * N + col) =
            make_float2(acc[mt][nt][0], acc[mt][nt][1]);
        *(float2*)(Cf + (size_t)(row + 8) * N + col) =
            make_float2(acc[mt][nt][2], acc[mt][nt][3]);
      } else {
        uint16_t h0, l0, h1, l1;
        split1(acc[mt][nt][0], h0, l0); split1(acc[mt][nt][1], h1, l1);
        *(uint32_t*)(Chi + (size_t)row * N + col) = h0 | ((uint32_t)h1 << 16);
        *(uint32_t*)(Clo + (size_t)row * N + col) = l0 | ((uint32_t)l1 << 16);
        split1(acc[mt][nt][2], h0, l0); split1(acc[mt][nt][3], h1, l1);
        *(uint32_t*)(Chi + (size_t)(row + 8) * N + col) = h0 | ((uint32_t)h1 << 16);
        *(uint32_t*)(Clo + (size_t)(row + 8) * N + col) = l0 | ((uint32_t)l1 << 16);
      }
    }
  }
}

// ---------------------------------------------------------------------------
// bf16x3 causal flash attention. CTA = 64 queries of one (b,h), 4 warps.
// Q fragments hoisted to registers; K via ldmatrix; P stays in registers;
// V transposed on load via ldmatrix.x4.trans. Pass-major MMA issue.
// SMEM: Qh 8K | Ql 8K | Kh x2 16K | Kl x2 16K | Vh x2 16K | Vl x2 16K = 80KB
// ---------------------------------------------------------------------------
#define AQH 0
#define AQL 8192
#define AKH 16384
#define AKL 32768
#define AVH 49152
#define AVL 65536
#define ASMEM_TOTAL 81920

__global__ __launch_bounds__(128) void attn3(
    const __nv_bfloat16* __restrict__ qh, const __nv_bfloat16* __restrict__ ql,
    __nv_bfloat16* __restrict__ oh, __nv_bfloat16* __restrict__ ol) {
  extern __shared__ char sm[];
  const int qi = blockIdx.x, h = blockIdx.y, b = blockIdx.z;
  const int tid = threadIdx.x, w = tid >> 5, lane = tid & 31;
  const int g = lane >> 2, t = lane & 3;
  const int q0 = qi * 64;
  const int r0 = w * 16 + g;
  const size_t rowQ = (size_t)(b * TT + q0);
  // ldmatrix lane geometry
  const int row16 = ((lane >> 3) & 1) * 8 + (lane & 7);
  const int khalf = lane >> 4;
  const uint32_t rx = (uint32_t)(lane & 7) << 4;
  const int qq = lane >> 3, rr = lane & 7;

  auto fillKV = [&](int kb, int bf) {
    const size_t base = (size_t)(b * TT + kb * 64) * 3 * CM + CM + h * 64;
    char* kh = sm + AKH + bf * 8192;
    char* kl = sm + AKL + bf * 8192;
    char* vh = sm + AVH + bf * 8192;
    char* vl = sm + AVL + bf * 8192;
#pragma unroll
    for (int i = tid; i < 512; i += 128) {
      int row = i >> 3, c = i & 7;
      uint32_t swo = sw128((uint32_t)(row * 128 + c * 16));
      size_t src = base + (size_t)row * 3 * CM + c * 8;
      cp16(smem_u32(kh + swo), qh + src);
      cp16(smem_u32(kl + swo), ql + src);
      cp16(smem_u32(vh + swo), qh + src + CM);
      cp16(smem_u32(vl + swo), ql + src + CM);
    }
  };

  // prologue: Q + KV block 0, one group
#pragma unroll
  for (int i = tid; i < 512; i += 128) {
    int row = i >> 3, c = i & 7;
    uint32_t swo = sw128((uint32_t)(row * 128 + c * 16));
    size_t src = (rowQ + row) * 3 * CM + h * 64 + c * 8;
    cp16(smem_u32(sm + AQH + swo), qh + src);
    cp16(smem_u32(sm + AQL + swo), ql + src);
  }
  fillKV(0, 0);
  CP_COMMIT();

  float m0 = -1e30f, m1 = -1e30f, l0 = 0.f, l1 = 0.f;
  float o[8][4];
#pragma unroll
  for (int j = 0; j < 8; j++)
#pragma unroll
    for (int r = 0; r < 4; r++) o[j][r] = 0.f;

  uint32_t qfh[4][4], qfl[4][4];   // hoisted Q fragments (per kt)

  for (int kj = 0; kj <= qi; kj++) {
    const int buf = kj & 1;
    if (kj < qi) fillKV(kj + 1, buf ^ 1);
    CP_COMMIT();
    CP_WAIT(1);
    __syncthreads();

    if (kj == 0) {   // Q resident now; hoist fragments once
      const uint32_t qhU = smem_u32(sm + AQH);
      const uint32_t qlU = smem_u32(sm + AQL);
#pragma unroll
      for (int kt = 0; kt < 4; kt++) {
        const uint32_t rel = (uint32_t)((w * 16 + row16) * 128)
                           + (((uint32_t)(kt * 32 + khalf * 16)) ^ rx);
        ldsm4(qfh[kt], qhU + rel);
        ldsm4(qfl[kt], qlU + rel);
      }
    }

    const uint32_t khU = smem_u32(sm + AKH + buf * 8192);
    const uint32_t klU = smem_u32(sm + AKL + buf * 8192);
    const uint32_t vhU = smem_u32(sm + AVH + buf * 8192);
    const uint32_t vlU = smem_u32(sm + AVL + buf * 8192);

    // ---- S = Q K^T (3-pass bf16) ----
    float s[8][4];
#pragma unroll
    for (int j = 0; j < 8; j++)
#pragma unroll
      for (int r = 0; r < 4; r++) s[j][r] = 0.f;

#pragma unroll
    for (int kt = 0; kt < 4; kt++) {
      const uint32_t colb = ((uint32_t)(kt * 32 + khalf * 16)) ^ rx;
      uint32_t kf[8][2];
#pragma unroll
      for (int jp2 = 0; jp2 < 4; jp2++) {
        uint32_t r[4];
        ldsm4(r, khU + (uint32_t)((jp2 * 16 + row16) * 128) + colb);
        kf[2*jp2][0] = r[0]; kf[2*jp2+1][0] = r[1];
        kf[2*jp2][1] = r[2]; kf[2*jp2+1][1] = r[3];
      }
#pragma unroll
      for (int j = 0; j < 8; j++) mma16(s[j], qfh[kt], kf[j][0], kf[j][1]);
#pragma unroll
      for (int j = 0; j < 8; j++) mma16(s[j], qfl[kt], kf[j][0], kf[j][1]);
#pragma unroll
      for (int jp2 = 0; jp2 < 4; jp2++) {
        uint32_t r[4];
        ldsm4(r, klU + (uint32_t)((jp2 * 16 + row16) * 128) + colb);
        kf[2*jp2][0] = r[0]; kf[2*jp2+1][0] = r[1];
        kf[2*jp2][1] = r[2]; kf[2*jp2+1][1] = r[3];
      }
#pragma unroll
      for (int j = 0; j < 8; j++) mma16(s[j], qfh[kt], kf[j][0], kf[j][1]);
    }

    // scale 1/sqrt(64), causal mask on diagonal block
#pragma unroll
    for (int j = 0; j < 8; j++)
#pragma unroll
      for (int r = 0; r < 4; r++) s[j][r] *= 0.125f;

    if (kj == qi) {
#pragma unroll
      for (int j = 0; j < 8; j++) {
        const int c = j * 8 + 2 * t;
        if (c     > r0)     s[j][0] = -1e30f;
        if (c + 1 > r0)     s[j][1] = -1e30f;
        if (c     > r0 + 8) s[j][2] = -1e30f;
        if (c + 1 > r0 + 8) s[j][3] = -1e30f;
      }
    }

    // ---- online softmax (rows r0, r0+8; 4 quad lanes share a row) ----
    float rm0 = -1e30f, rm1 = -1e30f;
#pragma unroll
    for (int j = 0; j < 8; j++) {
      rm0 = fmaxf(rm0, fmaxf(s[j][0], s[j][1]));
      rm1 = fmaxf(rm1, fmaxf(s[j][2], s[j][3]));
    }
    rm0 = fmaxf(rm0, __shfl_xor_sync(0xffffffffu, rm0, 1));
    rm0 = fmaxf(rm0, __shfl_xor_sync(0xffffffffu, rm0, 2));
    rm1 = fmaxf(rm1, __shfl_xor_sync(0xffffffffu, rm1, 1));
    rm1 = fmaxf(rm1, __shfl_xor_sync(0xffffffffu, rm1, 2));
    const float mn0 = fmaxf(m0, rm0), mn1 = fmaxf(m1, rm1);
    const float al_0 = __expf(m0 - mn0), al_1 = __expf(m1 - mn1);
    float rs0 = 0.f, rs1 = 0.f;
#pragma unroll
    for (int j = 0; j < 8; j++) {
      s[j][0] = __expf(s[j][0] - mn0);
      s[j][1] = __expf(s[j][1] - mn0);
      s[j][2] = __expf(s[j][2] - mn1);
      s[j][3] = __expf(s[j][3] - mn1);
      rs0 += s[j][0] + s[j][1];
      rs1 += s[j][2] + s[j][3];
    }
    rs0 += __shfl_xor_sync(0xffffffffu, rs0, 1);
    rs0 += __shfl_xor_sync(0xffffffffu, rs0, 2);
    rs1 += __shfl_xor_sync(0xffffffffu, rs1, 1);
    rs1 += __shfl_xor_sync(0xffffffffu, rs1, 2);
    l0 = l0 * al_0 + rs0;  m0 = mn0;
    l1 = l1 * al_1 + rs1;  m1 = mn1;
#pragma unroll
    for (int j = 0; j < 8; j++) {
      o[j][0] *= al_0; o[j][1] *= al_0;
      o[j][2] *= al_1; o[j][3] *= al_1;
    }

    // ---- split P in registers (accumulator layout == A-frag layout) ----
    uint32_t ph01[8], ph23[8], pl01[8], pl23[8];
#pragma unroll
    for (int j = 0; j < 8; j++) {
      uint16_t h0, l0_, h1, l1_;
      split1(s[j][0], h0, l0_); split1(s[j][1], h1, l1_);
      ph01[j] = h0 | ((uint32_t)h1 << 16);
      pl01[j] = l0_ | ((uint32_t)l1_ << 16);
      split1(s[j][2], h0, l0_); split1(s[j][3], h1, l1_);
      ph23[j] = h0 | ((uint32_t)h1 << 16);
      pl23[j] = l0_ | ((uint32_t)l1_ << 16);
    }

    // ---- O += P V (3-pass; V^T fragments via ldmatrix.x4.trans) ----
#pragma unroll
    for (int kt = 0; kt < 4; kt++) {
      const uint32_t pa[4] = {ph01[2*kt], ph23[2*kt], ph01[2*kt+1], ph23[2*kt+1]};
      const uint32_t qa[4] = {pl01[2*kt], pl23[2*kt], pl01[2*kt+1], pl23[2*kt+1]};
      const uint32_t vrow = (uint32_t)(kt * 16 + ((qq & 1) << 3) + rr);
      uint32_t vf[4][4];
#pragma unroll
      for (int jp = 0; jp < 4; jp++)
        ldsm4t(vf[jp], vhU + sw128(vrow * 128 + (uint32_t)(jp * 32 + ((qq >> 1) << 4))));
      // pass Ph x Vh
#pragma unroll
      for (int jp = 0; jp < 4; jp++) {
        mma16(o[2*jp],     pa, vf[jp][0], vf[jp][1]);
        mma16(o[2*jp + 1], pa, vf[jp][2], vf[jp][3]);
      }
      // pass Pl x Vh
#pragma unroll
      for (int jp = 0; jp < 4; jp++) {
        mma16(o[2*jp],     qa, vf[jp][0], vf[jp][1]);
        mma16(o[2*jp + 1], qa, vf[jp][2], vf[jp][3]);
      }
      // load Vl (Vh dead), pass Ph x Vl
#pragma unroll
      for (int jp = 0; jp < 4; jp++)
        ldsm4t(vf[jp], vlU + sw128(vrow * 128 + (uint32_t)(jp * 32 + ((qq >> 1) << 4))));
#pragma unroll
      for (int jp = 0; jp < 4; jp++) {
        mma16(o[2*jp],     pa, vf[jp][0], vf[jp][1]);
        mma16(o[2*jp + 1], pa, vf[jp][2], vf[jp][3]);
      }
    }
    __syncthreads();   // tiles consumed before next prefetch overwrites
  }

  // ---- epilogue: O /= l, split to hi/lo bf16 ----
  const float i0 = 1.f / l0, i1 = 1.f / l1;
  const size_t ro0 = (rowQ + r0) * CM + h * 64;
  const size_t ro1 = ro0 + 8 * (size_t)CM;
#pragma unroll
  for (int j = 0; j < 8; j++) {
    const int col = j * 8 + 2 * t;
    uint16_t h0, l0_, h1, l1_;
    split1(o[j][0] * i0, h0, l0_); split1(o[j][1] * i0, h1, l1_);
    *(uint32_t*)(oh + ro0 + col) = h0 | ((uint32_t)h1 << 16);
    *(uint32_t*)(ol + ro0 + col) = l0_ | ((uint32_t)l1_ << 16);
    split1(o[j][2] * i1, h0, l0_); split1(o[j][3] * i1, h1, l1_);
    *(uint32_t*)(oh + ro1 + col) = h0 | ((uint32_t)h1 << 16);
    *(uint32_t*)(ol + ro1 + col) = l0_ | ((uint32_t)l1_ << 16);
  }
}

// ---------------------------------------------------------------------------
extern "C" void kernel_launch(void* const* d_in, const int* in_sizes, int n_in,
                              void* d_out, int out_size) {
  const float* x     = (const float*)d_in[0];   // [4,2048,1024]
  const float* w_qkv = (const float*)d_in[1];   // [3072,1024]
  const float* w_out = (const float*)d_in[2];   // [1024,1024]
  float* out = (float*)d_out;

  __nv_bfloat16 *xh, *xl, *wqh, *wql, *woh, *wol, *qkvh, *qkvl, *ath, *atl;
  cudaGetSymbolAddress((void**)&xh,  g_x_hi);    cudaGetSymbolAddress((void**)&xl,  g_x_lo);
  cudaGetSymbolAddress((void**)&wqh, g_wqkv_hi); cudaGetSymbolAddress((void**)&wql, g_wqkv_lo);
  cudaGetSymbolAddress((void**)&woh, g_wout_hi); cudaGetSymbolAddress((void**)&wol, g_wout_lo);
  cudaGetSymbolAddress((void**)&qkvh, g_qkv_hi); cudaGetSymbolAddress((void**)&qkvl, g_qkv_lo);
  cudaGetSymbolAddress((void**)&ath, g_att_hi);  cudaGetSymbolAddress((void**)&atl, g_att_lo);

  cudaFuncSetAttribute(gemm3<0>, cudaFuncAttributeMaxDynamicSharedMemorySize, GSMEM_TOTAL);
  cudaFuncSetAttribute(gemm3<1>, cudaFuncAttributeMaxDynamicSharedMemorySize, GSMEM_TOTAL);
  cudaFuncSetAttribute(attn3,    cudaFuncAttributeMaxDynamicSharedMemorySize, ASMEM_TOTAL);

  // 0) split inputs into bf16 hi/lo
  {
    int n4 = MR * CM / 4;
    split_kernel<<<(n4 + 255) / 256, 256>>>(x, xh, xl, n4);
    n4 = 3 * CM * CM / 4;
    split_kernel<<<(n4 + 255) / 256, 256>>>(w_qkv, wqh, wql, n4);
    n4 = CM * CM / 4;
    split_kernel<<<(n4 + 255) / 256, 256>>>(w_out, woh, wol, n4);
  }

  // 1) QKV projection -> qkv hi/lo bf16
  gemm3<1><<<dim3(3*CM/128, MR/128), 256, GSMEM_TOTAL>>>(
      xh, xl, wqh, wql, nullptr, qkvh, qkvl, 3*CM, CM);

  // 2) causal flash attention -> att hi/lo bf16
  attn3<<<dim3(TT/64, HH, BB), 128, ASMEM_TOTAL>>>(qkvh, qkvl, ath, atl);

  // 3) output projection -> fp32 out
  gemm3<0><<<dim3(CM/128, MR/128), 256, GSMEM_TOTAL>>>(
      ath, atl, woh, wol, out, nullptr, nullptr, CM, CM);
}

// round 6
// speedup vs baseline: 1.0183x; 1.0183x over previous
#include <cuda_runtime.h>
#include <cuda_bf16.h>
#include <cstdint>

#define CM 1024
#define TT 2048
#define BB 4
#define HH 16
#define MR (BB*TT)   // 8192 rows

// ---------------------------------------------------------------------------
// Scratch (device globals: allocation-free per harness rules)
// ---------------------------------------------------------------------------
__device__ __nv_bfloat16 g_x_hi[(size_t)MR * CM],     g_x_lo[(size_t)MR * CM];
__device__ __nv_bfloat16 g_wqkv_hi[3 * CM * CM],      g_wqkv_lo[3 * CM * CM];
__device__ __nv_bfloat16 g_wout_hi[CM * CM],          g_wout_lo[CM * CM];
__device__ __nv_bfloat16 g_qkv_hi[(size_t)MR * 3 * CM], g_qkv_lo[(size_t)MR * 3 * CM];
__device__ __nv_bfloat16 g_att_hi[(size_t)MR * CM],   g_att_lo[(size_t)MR * CM];

// ---------------------------------------------------------------------------
// helpers
// ---------------------------------------------------------------------------
__device__ __forceinline__ uint32_t smem_u32(const void* p) {
  uint32_t a;
  asm("{ .reg .u64 t; cvta.to.shared.u64 t, %1; cvt.u32.u64 %0, t; }"
      : "=r"(a) : "l"(p));
  return a;
}
__device__ __forceinline__ void cp16(uint32_t s, const void* g) {
  asm volatile("cp.async.cg.shared.global [%0], [%1], 16;" :: "r"(s), "l"(g));
}
#define CP_COMMIT() asm volatile("cp.async.commit_group;" ::: "memory")
#define CP_WAIT(n)  asm volatile("cp.async.wait_group %0;" :: "n"(n) : "memory")

// D += A*B, m16n8k16 bf16, fp32 accumulate
__device__ __forceinline__ void mma16(float* d, uint32_t a0, uint32_t a1,
                                      uint32_t a2, uint32_t a3,
                                      uint32_t b0, uint32_t b1) {
  asm volatile(
      "mma.sync.aligned.m16n8k16.row.col.f32.bf16.bf16.f32 "
      "{%0,%1,%2,%3}, {%4,%5,%6,%7}, {%8,%9}, {%0,%1,%2,%3};"
      : "+f"(d[0]), "+f"(d[1]), "+f"(d[2]), "+f"(d[3])
      : "r"(a0), "r"(a1), "r"(a2), "r"(a3), "r"(b0), "r"(b1));
}
__device__ __forceinline__ void ldsm4t(uint32_t& r0, uint32_t& r1,
                                       uint32_t& r2, uint32_t& r3, uint32_t a) {
  asm volatile("ldmatrix.sync.aligned.m8n8.x4.trans.shared.b16 "
               "{%0,%1,%2,%3}, [%4];"
               : "=r"(r0), "=r"(r1), "=r"(r2), "=r"(r3) : "r"(a));
}
__device__ __forceinline__ uint32_t ldu(const void* p) {
  return *(const uint32_t*)p;
}
__device__ __forceinline__ uint32_t sw128(uint32_t o) { return o ^ ((o >> 3) & 0x70); }

// split fp32 -> bf16 hi + bf16 lo (x = hi + lo + O(2^-18 x))
__device__ __forceinline__ void split1(float x, uint16_t& h, uint16_t& l) {
  __nv_bfloat16 bh = __float2bfloat16_rn(x);
  float r = x - __bfloat162float(bh);
  __nv_bfloat16 bl = __float2bfloat16_rn(r);
  h = __bfloat16_as_ushort(bh);
  l = __bfloat16_as_ushort(bl);
}

// ---------------------------------------------------------------------------
// elementwise split: fp32 -> (hi, lo) bf16
// ---------------------------------------------------------------------------
__global__ __launch_bounds__(256) void split_kernel(
    const float* __restrict__ in, __nv_bfloat16* __restrict__ hi,
    __nv_bfloat16* __restrict__ lo, int n4) {
  int i = blockIdx.x * blockDim.x + threadIdx.x;
  if (i >= n4) return;
  float4 v = ((const float4*)in)[i];
  uint16_t h0, h1, h2, h3, l0, l1, l2, l3;
  split1(v.x, h0, l0); split1(v.y, h1, l1);
  split1(v.z, h2, l2); split1(v.w, h3, l3);
  ((uint2*)hi)[i] = make_uint2(h0 | ((uint32_t)h1 << 16), h2 | ((uint32_t)h3 << 16));
  ((uint2*)lo)[i] = make_uint2(l0 | ((uint32_t)l1 << 16), l2 | ((uint32_t)l3 << 16));
}

// ---------------------------------------------------------------------------
// bf16x3 TN GEMM: C[M,N] = A[M,K] * B[N,K]^T, A/B given as bf16 hi/lo pairs.
// CTA 128x128, BK=32, 3-stage cp.async, 256 threads (8 warps: 2x4, 64x32 each)
// SMEM row (128B) = [hi k0 | hi k1 | lo k0 | lo k1] -> stage 32KB, 2 CTAs/SM.
// MODE 0: write fp32 C.  MODE 1: write bf16 hi/lo C.
// ---------------------------------------------------------------------------
#define GST 3
#define STB 32768                       // stage bytes: A 16K + B 16K
#define GSMEM_TOTAL (GST * STB)         // 96 KB

template<int MODE>
__global__ __launch_bounds__(256, 2) void gemm3(
    const __nv_bfloat16* __restrict__ Ah_, const __nv_bfloat16* __restrict__ Al_,
    const __nv_bfloat16* __restrict__ Bh_, const __nv_bfloat16* __restrict__ Bl_,
    float* __restrict__ Cf, __nv_bfloat16* __restrict__ Chi,
    __nv_bfloat16* __restrict__ Clo, int N, int K) {
  extern __shared__ char sm[];
  const int tid = threadIdx.x, w = tid >> 5, lane = tid & 31;
  const int g = lane >> 2, t = lane & 3;
  const int wm = w & 1, wn = w >> 1;
  const int bm = blockIdx.y * 128, bn = blockIdx.x * 128;

  float acc[4][4][4];
#pragma unroll
  for (int mt = 0; mt < 4; mt++)
#pragma unroll
    for (int nt = 0; nt < 4; nt++)
#pragma unroll
      for (int r = 0; r < 4; r++) acc[mt][nt][r] = 0.f;

  // stage fill: A rows then B rows; row 128B = [hi0|hi1|lo0|lo1] 32B chunks
  auto fill = [&](int s, int k0) {
    char* base = sm + s * STB;
#pragma unroll
    for (int i = tid; i < 2048; i += 256) {
      int buf = i >> 10;            // 0 = A, 1 = B
      int row = (i >> 3) & 127;
      int c = i & 7;                // granule: 0-3 hi, 4-7 lo
      uint32_t swo = sw128((uint32_t)(row * 128 + c * 16));
      size_t off = (size_t)((buf ? bn : bm) + row) * K + k0 + (c & 3) * 8;
      const __nv_bfloat16* src =
          buf ? ((c < 4) ? Bh_ : Bl_) + off : ((c < 4) ? Ah_ : Al_) + off;
      cp16(smem_u32(base + buf * 16384 + swo), src);
    }
  };

  const int KT = K >> 5;            // 32
  fill(0, 0);  CP_COMMIT();
  fill(1, 32); CP_COMMIT();
  fill(2, 64); CP_COMMIT();

  const uint32_t xg = (uint32_t)g << 4;

  for (int c = 0; c < KT; c++) {
    const int s = c - (c / 3) * 3;
    CP_WAIT(2);
    __syncthreads();
    const char* A0 = sm + s * STB;
    const char* B0 = A0 + 16384;
#pragma unroll
    for (int kt = 0; kt < 2; kt++) {
      const uint32_t xo = ((uint32_t)(kt * 32 + t * 4)) ^ xg;
      uint32_t ah[4][4], al[4][4];
#pragma unroll
      for (int mt = 0; mt < 4; mt++) {
        const char* ar = A0 + (wm * 64 + mt * 16 + g) * 128;
        ah[mt][0] = ldu(ar + xo);
        ah[mt][1] = ldu(ar + 1024 + xo);
        ah[mt][2] = ldu(ar + (xo ^ 16));
        ah[mt][3] = ldu(ar + 1024 + (xo ^ 16));
        al[mt][0] = ldu(ar + (xo ^ 64));
        al[mt][1] = ldu(ar + 1024 + (xo ^ 64));
        al[mt][2] = ldu(ar + (xo ^ 64 ^ 16));
        al[mt][3] = ldu(ar + 1024 + (xo ^ 64 ^ 16));
      }
#pragma unroll
      for (int nt = 0; nt < 4; nt++) {
        const char* br = B0 + (wn * 32 + nt * 8 + g) * 128;
        uint32_t bh0 = ldu(br + xo),        bh1 = ldu(br + (xo ^ 16));
        uint32_t bl0 = ldu(br + (xo ^ 64)), bl1 = ldu(br + (xo ^ 64 ^ 16));
#pragma unroll
        for (int mt = 0; mt < 4; mt++) {
          mma16(acc[mt][nt], ah[mt][0], ah[mt][1], ah[mt][2], ah[mt][3], bh0, bh1);
          mma16(acc[mt][nt], ah[mt][0], ah[mt][1], ah[mt][2], ah[mt][3], bl0, bl1);
          mma16(acc[mt][nt], al[mt][0], al[mt][1], al[mt][2], al[mt][3], bh0, bh1);
        }
      }
    }
    __syncthreads();
    if (c + 3 < KT) fill(s, (c + 3) * 32);
    CP_COMMIT();
  }

#pragma unroll
  for (int mt = 0; mt < 4; mt++) {
#pragma unroll
    for (int nt = 0; nt < 4; nt++) {
      const int row = bm + wm * 64 + mt * 16 + g;
      const int col = bn + wn * 32 + nt * 8 + 2 * t;
      if (MODE == 0) {
        *(float2*)(Cf + (size_t)row * N + col) =
            make_float2(acc[mt][nt][0], acc[mt][nt][1]);
        *(float2*)(Cf + (size_t)(row + 8) * N + col) =
            make_float2(acc[mt][nt][2], acc[mt][nt][3]);
      } else {
        uint16_t h0, l0, h1, l1;
        split1(acc[mt][nt][0], h0, l0); split1(acc[mt][nt][1], h1, l1);
        *(uint32_t*)(Chi + (size_t)row * N + col) = h0 | ((uint32_t)h1 << 16);
        *(uint32_t*)(Clo + (size_t)row * N + col) = l0 | ((uint32_t)l1 << 16);
        split1(acc[mt][nt][2], h0, l0); split1(acc[mt][nt][3], h1, l1);
        *(uint32_t*)(Chi + (size_t)(row + 8) * N + col) = h0 | ((uint32_t)h1 << 16);
        *(uint32_t*)(Clo + (size_t)(row + 8) * N + col) = l0 | ((uint32_t)l1 << 16);
      }
    }
  }
}

// ---------------------------------------------------------------------------
// bf16x3 causal flash attention (R4 version, best measured).
// CTA = 64 queries of one (b,h), 4 warps. P stays in registers.
// SMEM: Qh 8K | Ql 8K | Kh x2 16K | Kl x2 16K | Vh x2 16K | Vl x2 16K = 80KB
// ---------------------------------------------------------------------------
#define AQH 0
#define AQL 8192
#define AKH 16384
#define AKL 32768
#define AVH 49152
#define AVL 65536
#define ASMEM_TOTAL 81920

__global__ __launch_bounds__(128) void attn3(
    const __nv_bfloat16* __restrict__ qh, const __nv_bfloat16* __restrict__ ql,
    __nv_bfloat16* __restrict__ oh, __nv_bfloat16* __restrict__ ol) {
  extern __shared__ char sm[];
  const int qi = blockIdx.x, h = blockIdx.y, b = blockIdx.z;
  const int tid = threadIdx.x, w = tid >> 5, lane = tid & 31;
  const int g = lane >> 2, t = lane & 3;
  const int q0 = qi * 64;
  const int r0 = w * 16 + g;
  const size_t rowQ = (size_t)(b * TT + q0);

  auto fillKV = [&](int kb, int bf) {
    const size_t base = (size_t)(b * TT + kb * 64) * 3 * CM + CM + h * 64;
    char* kh = sm + AKH + bf * 8192;
    char* kl = sm + AKL + bf * 8192;
    char* vh = sm + AVH + bf * 8192;
    char* vl = sm + AVL + bf * 8192;
#pragma unroll
    for (int i = tid; i < 512; i += 128) {
      int row = i >> 3, c = i & 7;
      uint32_t swo = sw128((uint32_t)(row * 128 + c * 16));
      size_t src = base + (size_t)row * 3 * CM + c * 8;
      cp16(smem_u32(kh + swo), qh + src);
      cp16(smem_u32(kl + swo), ql + src);
      cp16(smem_u32(vh + swo), qh + src + CM);
      cp16(smem_u32(vl + swo), ql + src + CM);
    }
  };

  // prologue: Q + KV block 0, one group
#pragma unroll
  for (int i = tid; i < 512; i += 128) {
    int row = i >> 3, c = i & 7;
    uint32_t swo = sw128((uint32_t)(row * 128 + c * 16));
    size_t src = (rowQ + row) * 3 * CM + h * 64 + c * 8;
    cp16(smem_u32(sm + AQH + swo), qh + src);
    cp16(smem_u32(sm + AQL + swo), ql + src);
  }
  fillKV(0, 0);
  CP_COMMIT();

  float m0 = -1e30f, m1 = -1e30f, l0 = 0.f, l1 = 0.f;
  float o[8][4];
#pragma unroll
  for (int j = 0; j < 8; j++)
#pragma unroll
    for (int r = 0; r < 4; r++) o[j][r] = 0.f;

  const uint32_t xg = (uint32_t)g << 4;

  for (int kj = 0; kj <= qi; kj++) {
    const int buf = kj & 1;
    if (kj < qi) fillKV(kj + 1, buf ^ 1);
    CP_COMMIT();
    CP_WAIT(1);
    __syncthreads();

    const char* Kh = sm + AKH + buf * 8192;
    const char* Kl = sm + AKL + buf * 8192;
    const char* Qh = sm + AQH;
    const char* Ql = sm + AQL;
    const uint32_t vhU = smem_u32(sm + AVH + buf * 8192);
    const uint32_t vlU = smem_u32(sm + AVL + buf * 8192);

    // ---- S = Q K^T (3-pass bf16) ----
    float s[8][4];
#pragma unroll
    for (int j = 0; j < 8; j++)
#pragma unroll
      for (int r = 0; r < 4; r++) s[j][r] = 0.f;

#pragma unroll
    for (int kt = 0; kt < 4; kt++) {
      const uint32_t xo = ((uint32_t)(kt * 32 + t * 4)) ^ xg;
      const char* qrh = Qh + r0 * 128;
      const char* qrl = Ql + r0 * 128;
      uint32_t ah0 = ldu(qrh + xo),        ah1 = ldu(qrh + 1024 + xo);
      uint32_t ah2 = ldu(qrh + (xo ^ 16)), ah3 = ldu(qrh + 1024 + (xo ^ 16));
      uint32_t al0 = ldu(qrl + xo),        al1 = ldu(qrl + 1024 + xo);
      uint32_t al2 = ldu(qrl + (xo ^ 16)), al3 = ldu(qrl + 1024 + (xo ^ 16));
#pragma unroll
      for (int j = 0; j < 8; j++) {
        const char* krh = Kh + (j * 8 + g) * 128;
        const char* krl = Kl + (j * 8 + g) * 128;
        uint32_t bh0 = ldu(krh + xo), bh1 = ldu(krh + (xo ^ 16));
        uint32_t bl0 = ldu(krl + xo), bl1 = ldu(krl + (xo ^ 16));
        mma16(s[j], ah0, ah1, ah2, ah3, bh0, bh1);
        mma16(s[j], ah0, ah1, ah2, ah3, bl0, bl1);
        mma16(s[j], al0, al1, al2, al3, bh0, bh1);
      }
    }

    // scale 1/sqrt(64), causal mask on diagonal block
#pragma unroll
    for (int j = 0; j < 8; j++)
#pragma unroll
      for (int r = 0; r < 4; r++) s[j][r] *= 0.125f;

    if (kj == qi) {
#pragma unroll
      for (int j = 0; j < 8; j++) {
        const int c = j * 8 + 2 * t;
        if (c     > r0)     s[j][0] = -1e30f;
        if (c + 1 > r0)     s[j][1] = -1e30f;
        if (c     > r0 + 8) s[j][2] = -1e30f;
        if (c + 1 > r0 + 8) s[j][3] = -1e30f;
      }
    }

    // ---- online softmax (rows r0, r0+8; 4 quad lanes share a row) ----
    float rm0 = -1e30f, rm1 = -1e30f;
#pragma unroll
    for (int j = 0; j < 8; j++) {
      rm0 = fmaxf(rm0, fmaxf(s[j][0], s[j][1]));
      rm1 = fmaxf(rm1, fmaxf(s[j][2], s[j][3]));
    }
    rm0 = fmaxf(rm0, __shfl_xor_sync(0xffffffffu, rm0, 1));
    rm0 = fmaxf(rm0, __shfl_xor_sync(0xffffffffu, rm0, 2));
    rm1 = fmaxf(rm1, __shfl_xor_sync(0xffffffffu, rm1, 1));
    rm1 = fmaxf(rm1, __shfl_xor_sync(0xffffffffu, rm1, 2));
    const float mn0 = fmaxf(m0, rm0), mn1 = fmaxf(m1, rm1);
    const float al_0 = __expf(m0 - mn0), al_1 = __expf(m1 - mn1);
    float rs0 = 0.f, rs1 = 0.f;
#pragma unroll
    for (int j = 0; j < 8; j++) {
      s[j][0] = __expf(s[j][0] - mn0);
      s[j][1] = __expf(s[j][1] - mn0);
      s[j][2] = __expf(s[j][2] - mn1);
      s[j][3] = __expf(s[j][3] - mn1);
      rs0 += s[j][0] + s[j][1];
      rs1 += s[j][2] + s[j][3];
    }
    rs0 += __shfl_xor_sync(0xffffffffu, rs0, 1);
    rs0 += __shfl_xor_sync(0xffffffffu, rs0, 2);
    rs1 += __shfl_xor_sync(0xffffffffu, rs1, 1);
    rs1 += __shfl_xor_sync(0xffffffffu, rs1, 2);
    l0 = l0 * al_0 + rs0;  m0 = mn0;
    l1 = l1 * al_1 + rs1;  m1 = mn1;
#pragma unroll
    for (int j = 0; j < 8; j++) {
      o[j][0] *= al_0; o[j][1] *= al_0;
      o[j][2] *= al_1; o[j][3] *= al_1;
    }

    // ---- split P in registers (accumulator layout == A-frag layout) ----
    uint32_t ph01[8], ph23[8], pl01[8], pl23[8];
#pragma unroll
    for (int j = 0; j < 8; j++) {
      uint16_t h0, l0_, h1, l1_;
      split1(s[j][0], h0, l0_); split1(s[j][1], h1, l1_);
      ph01[j] = h0 | ((uint32_t)h1 << 16);
      pl01[j] = l0_ | ((uint32_t)l1_ << 16);
      split1(s[j][2], h0, l0_); split1(s[j][3], h1, l1_);
      ph23[j] = h0 | ((uint32_t)h1 << 16);
      pl23[j] = l0_ | ((uint32_t)l1_ << 16);
    }

    // ---- O += P V (3-pass; V^T fragments via ldmatrix.x4.trans) ----
    const int qq = lane >> 3, rr = lane & 7;
#pragma unroll
    for (int kt = 0; kt < 4; kt++) {
      const uint32_t pa0 = ph01[2*kt],   pa1 = ph23[2*kt];
      const uint32_t pa2 = ph01[2*kt+1], pa3 = ph23[2*kt+1];
      const uint32_t qa0 = pl01[2*kt],   qa1 = pl23[2*kt];
      const uint32_t qa2 = pl01[2*kt+1], qa3 = pl23[2*kt+1];
      const uint32_t vrow = (uint32_t)(kt * 16 + ((qq & 1) << 3) + rr);
#pragma unroll
      for (int jp = 0; jp < 4; jp++) {
        const uint32_t off = sw128(vrow * 128 + (uint32_t)(jp * 32 + ((qq >> 1) << 4)));
        uint32_t vh0, vh1, vh2, vh3, vl0, vl1, vl2, vl3;
        ldsm4t(vh0, vh1, vh2, vh3, vhU + off);
        ldsm4t(vl0, vl1, vl2, vl3, vlU + off);
        mma16(o[2*jp],     pa0, pa1, pa2, pa3, vh0, vh1);
        mma16(o[2*jp],     pa0, pa1, pa2, pa3, vl0, vl1);
        mma16(o[2*jp],     qa0, qa1, qa2, qa3, vh0, vh1);
        mma16(o[2*jp + 1], pa0, pa1, pa2, pa3, vh2, vh3);
        mma16(o[2*jp + 1], pa0, pa1, pa2, pa3, vl2, vl3);
        mma16(o[2*jp + 1], qa0, qa1, qa2, qa3, vh2, vh3);
      }
    }
    __syncthreads();   // tiles consumed before next prefetch overwrites
  }

  // ---- epilogue: O /= l, split to hi/lo bf16 ----
  const float i0 = 1.f / l0, i1 = 1.f / l1;
  const size_t ro0 = (rowQ + r0) * CM + h * 64;
  const size_t ro1 = ro0 + 8 * (size_t)CM;
#pragma unroll
  for (int j = 0; j < 8; j++) {
    const int col = j * 8 + 2 * t;
    uint16_t h0, l0_, h1, l1_;
    split1(o[j][0] * i0, h0, l0_); split1(o[j][1] * i0, h1, l1_);
    *(uint32_t*)(oh + ro0 + col) = h0 | ((uint32_t)h1 << 16);
    *(uint32_t*)(ol + ro0 + col) = l0_ | ((uint32_t)l1_ << 16);
    split1(o[j][2] * i1, h0, l0_); split1(o[j][3] * i1, h1, l1_);
    *(uint32_t*)(oh + ro1 + col) = h0 | ((uint32_t)h1 << 16);
    *(uint32_t*)(ol + ro1 + col) = l0_ | ((uint32_t)l1_ << 16);
  }
}

// ---------------------------------------------------------------------------
extern "C" void kernel_launch(void* const* d_in, const int* in_sizes, int n_in,
                              void* d_out, int out_size) {
  const float* x     = (const float*)d_in[0];   // [4,2048,1024]
  const float* w_qkv = (const float*)d_in[1];   // [3072,1024]
  const float* w_out = (const float*)d_in[2];   // [1024,1024]
  float* out = (float*)d_out;

  __nv_bfloat16 *xh, *xl, *wqh, *wql, *woh, *wol, *qkvh, *qkvl, *ath, *atl;
  cudaGetSymbolAddress((void**)&xh,  g_x_hi);    cudaGetSymbolAddress((void**)&xl,  g_x_lo);
  cudaGetSymbolAddress((void**)&wqh, g_wqkv_hi); cudaGetSymbolAddress((void**)&wql, g_wqkv_lo);
  cudaGetSymbolAddress((void**)&woh, g_wout_hi); cudaGetSymbolAddress((void**)&wol, g_wout_lo);
  cudaGetSymbolAddress((void**)&qkvh, g_qkv_hi); cudaGetSymbolAddress((void**)&qkvl, g_qkv_lo);
  cudaGetSymbolAddress((void**)&ath, g_att_hi);  cudaGetSymbolAddress((void**)&atl, g_att_lo);

  cudaFuncSetAttribute(gemm3<0>, cudaFuncAttributeMaxDynamicSharedMemorySize, GSMEM_TOTAL);
  cudaFuncSetAttribute(gemm3<1>, cudaFuncAttributeMaxDynamicSharedMemorySize, GSMEM_TOTAL);
  cudaFuncSetAttribute(attn3,    cudaFuncAttributeMaxDynamicSharedMemorySize, ASMEM_TOTAL);

  // 0) split inputs into bf16 hi/lo
  {
    int n4 = MR * CM / 4;
    split_kernel<<<(n4 + 255) / 256, 256>>>(x, xh, xl, n4);
    n4 = 3 * CM * CM / 4;
    split_kernel<<<(n4 + 255) / 256, 256>>>(w_qkv, wqh, wql, n4);
    n4 = CM * CM / 4;
    split_kernel<<<(n4 + 255) / 256, 256>>>(w_out, woh, wol, n4);
  }

  // 1) QKV projection -> qkv hi/lo bf16
  gemm3<1><<<dim3(3*CM/128, MR/128), 256, GSMEM_TOTAL>>>(
      xh, xl, wqh, wql, nullptr, qkvh, qkvl, 3*CM, CM);

  // 2) causal flash attention -> att hi/lo bf16
  attn3<<<dim3(TT/64, HH, BB), 128, ASMEM_TOTAL>>>(qkvh, qkvl, ath, atl);

  // 3) output projection -> fp32 out
  gemm3<0><<<dim3(CM/128, MR/128), 256, GSMEM_TOTAL>>>(
      ath, atl, woh, wol, out, nullptr, nullptr, CM, CM);
}

// round 7
// speedup vs baseline: 1.0788x; 1.0595x over previous
#include <cuda_runtime.h>
#include <cuda_bf16.h>
#include <cstdint>

#define CM 1024
#define TT 2048
#define BB 4
#define HH 16
#define MR (BB*TT)   // 8192 rows

// ---------------------------------------------------------------------------
// Scratch (device globals: allocation-free per harness rules)
// ---------------------------------------------------------------------------
__device__ __nv_bfloat16 g_x_hi[(size_t)MR * CM],     g_x_lo[(size_t)MR * CM];
__device__ __nv_bfloat16 g_wqkv_hi[3 * CM * CM],      g_wqkv_lo[3 * CM * CM];
__device__ __nv_bfloat16 g_wout_hi[CM * CM],          g_wout_lo[CM * CM];
__device__ __nv_bfloat16 g_qkv_hi[(size_t)MR * 3 * CM], g_qkv_lo[(size_t)MR * 3 * CM];
__device__ __nv_bfloat16 g_att_hi[(size_t)MR * CM],   g_att_lo[(size_t)MR * CM];

// ---------------------------------------------------------------------------
// helpers
// ---------------------------------------------------------------------------
__device__ __forceinline__ uint32_t smem_u32(const void* p) {
  uint32_t a;
  asm("{ .reg .u64 t; cvta.to.shared.u64 t, %1; cvt.u32.u64 %0, t; }"
      : "=r"(a) : "l"(p));
  return a;
}
__device__ __forceinline__ void cp16(uint32_t s, const void* g) {
  asm volatile("cp.async.cg.shared.global [%0], [%1], 16;" :: "r"(s), "l"(g));
}
#define CP_COMMIT() asm volatile("cp.async.commit_group;" ::: "memory")
#define CP_WAIT(n)  asm volatile("cp.async.wait_group %0;" :: "n"(n) : "memory")

// D += A*B, m16n8k16 bf16, fp32 accumulate
__device__ __forceinline__ void mma16(float* d, uint32_t a0, uint32_t a1,
                                      uint32_t a2, uint32_t a3,
                                      uint32_t b0, uint32_t b1) {
  asm volatile(
      "mma.sync.aligned.m16n8k16.row.col.f32.bf16.bf16.f32 "
      "{%0,%1,%2,%3}, {%4,%5,%6,%7}, {%8,%9}, {%0,%1,%2,%3};"
      : "+f"(d[0]), "+f"(d[1]), "+f"(d[2]), "+f"(d[3])
      : "r"(a0), "r"(a1), "r"(a2), "r"(a3), "r"(b0), "r"(b1));
}
__device__ __forceinline__ void ldsm4t(uint32_t& r0, uint32_t& r1,
                                       uint32_t& r2, uint32_t& r3, uint32_t a) {
  asm volatile("ldmatrix.sync.aligned.m8n8.x4.trans.shared.b16 "
               "{%0,%1,%2,%3}, [%4];"
               : "=r"(r0), "=r"(r1), "=r"(r2), "=r"(r3) : "r"(a));
}
__device__ __forceinline__ uint32_t ldu(const void* p) {
  return *(const uint32_t*)p;
}
__device__ __forceinline__ uint32_t sw128(uint32_t o) { return o ^ ((o >> 3) & 0x70); }

// split fp32 -> bf16 hi + bf16 lo (x = hi + lo + O(2^-18 x))
__device__ __forceinline__ void split1(float x, uint16_t& h, uint16_t& l) {
  __nv_bfloat16 bh = __float2bfloat16_rn(x);
  float r = x - __bfloat162float(bh);
  __nv_bfloat16 bl = __float2bfloat16_rn(r);
  h = __bfloat16_as_ushort(bh);
  l = __bfloat16_as_ushort(bl);
}

// ---------------------------------------------------------------------------
// elementwise split: fp32 -> (hi, lo) bf16
// ---------------------------------------------------------------------------
__global__ __launch_bounds__(256) void split_kernel(
    const float* __restrict__ in, __nv_bfloat16* __restrict__ hi,
    __nv_bfloat16* __restrict__ lo, int n4) {
  int i = blockIdx.x * blockDim.x + threadIdx.x;
  if (i >= n4) return;
  float4 v = ((const float4*)in)[i];
  uint16_t h0, h1, h2, h3, l0, l1, l2, l3;
  split1(v.x, h0, l0); split1(v.y, h1, l1);
  split1(v.z, h2, l2); split1(v.w, h3, l3);
  ((uint2*)hi)[i] = make_uint2(h0 | ((uint32_t)h1 << 16), h2 | ((uint32_t)h3 << 16));
  ((uint2*)lo)[i] = make_uint2(l0 | ((uint32_t)l1 << 16), l2 | ((uint32_t)l3 << 16));
}

// ---------------------------------------------------------------------------
// bf16x3 TN GEMM: C[M,N] = A[M,K] * B[N,K]^T, A/B given as bf16 hi/lo pairs.
// CTA 128x128, BK=64, 3-stage cp.async, 256 threads (8 warps: 2x4, 64x32 each)
// Explicit register double-buffering across kt: fragment loads for kt+1 are
// issued BEFORE the MMAs of kt, breaking the lockstep load/MMA phase pattern.
// MODE 0: write fp32 C.  MODE 1: write bf16 hi/lo C.
// ---------------------------------------------------------------------------
#define GSMEM_TOTAL (3 * 65536)

template<int MODE>
__global__ __launch_bounds__(256) void gemm3(
    const __nv_bfloat16* __restrict__ Ah_, const __nv_bfloat16* __restrict__ Al_,
    const __nv_bfloat16* __restrict__ Bh_, const __nv_bfloat16* __restrict__ Bl_,
    float* __restrict__ Cf, __nv_bfloat16* __restrict__ Chi,
    __nv_bfloat16* __restrict__ Clo, int N, int K) {
  extern __shared__ char sm[];
  const int tid = threadIdx.x, w = tid >> 5, lane = tid & 31;
  const int g = lane >> 2, t = lane & 3;
  const int wm = w & 1, wn = w >> 1;
  const int bm = blockIdx.y * 128, bn = blockIdx.x * 128;

  float acc[4][4][4];
#pragma unroll
  for (int mt = 0; mt < 4; mt++)
#pragma unroll
    for (int nt = 0; nt < 4; nt++)
#pragma unroll
      for (int r = 0; r < 4; r++) acc[mt][nt][r] = 0.f;

  // stage: Ah | Al | Bh | Bl, each 128 rows x 128B (64 bf16), SW128 swizzled
  auto fill = [&](int s, int k0) {
    char* base = sm + s * 65536;
#pragma unroll
    for (int i = tid; i < 1024; i += 256) {
      int row = i >> 3, c = i & 7;
      uint32_t swo = sw128((uint32_t)(row * 128 + c * 16));
      size_t ao = (size_t)(bm + row) * K + k0 + c * 8;
      size_t bo = (size_t)(bn + row) * K + k0 + c * 8;
      cp16(smem_u32(base + swo),         Ah_ + ao);
      cp16(smem_u32(base + 16384 + swo), Al_ + ao);
      cp16(smem_u32(base + 32768 + swo), Bh_ + bo);
      cp16(smem_u32(base + 49152 + swo), Bl_ + bo);
    }
  };

  const int KT = K >> 6;
  fill(0, 0);   CP_COMMIT();
  fill(1, 64);  CP_COMMIT();
  fill(2, 128); CP_COMMIT();

  const uint32_t xg = (uint32_t)g << 4;

  for (int c = 0; c < KT; c++) {
    const int s = c - (c / 3) * 3;
    CP_WAIT(2);
    __syncthreads();
    const char* Ah = sm + s * 65536;
    const char* Al = Ah + 16384;
    const char* Bh = Ah + 32768;
    const char* Bl = Ah + 49152;

    // fragment register double-buffers
    uint32_t ah[2][4][4], al[2][4][4], bh[2][4][2], bl[2][4][2];

    auto loadFrags = [&](int kt, int buf) {
      const uint32_t xo = ((uint32_t)(kt * 32 + t * 4)) ^ xg;
#pragma unroll
      for (int mt = 0; mt < 4; mt++) {
        const char* ar  = Ah + (wm * 64 + mt * 16 + g) * 128;
        const char* arl = Al + (wm * 64 + mt * 16 + g) * 128;
        ah[buf][mt][0] = ldu(ar + xo);
        ah[buf][mt][1] = ldu(ar + 1024 + xo);
        ah[buf][mt][2] = ldu(ar + (xo ^ 16));
        ah[buf][mt][3] = ldu(ar + 1024 + (xo ^ 16));
        al[buf][mt][0] = ldu(arl + xo);
        al[buf][mt][1] = ldu(arl + 1024 + xo);
        al[buf][mt][2] = ldu(arl + (xo ^ 16));
        al[buf][mt][3] = ldu(arl + 1024 + (xo ^ 16));
      }
#pragma unroll
      for (int nt = 0; nt < 4; nt++) {
        const char* br  = Bh + (wn * 32 + nt * 8 + g) * 128;
        const char* brl = Bl + (wn * 32 + nt * 8 + g) * 128;
        bh[buf][nt][0] = ldu(br + xo);
        bh[buf][nt][1] = ldu(br + (xo ^ 16));
        bl[buf][nt][0] = ldu(brl + xo);
        bl[buf][nt][1] = ldu(brl + (xo ^ 16));
      }
    };

    loadFrags(0, 0);
#pragma unroll
    for (int kt = 0; kt < 4; kt++) {
      const int cur = kt & 1;
      if (kt < 3) loadFrags(kt + 1, cur ^ 1);   // prefetch next kt's fragments
#pragma unroll
      for (int nt = 0; nt < 4; nt++) {
#pragma unroll
        for (int mt = 0; mt < 4; mt++) {
          mma16(acc[mt][nt], ah[cur][mt][0], ah[cur][mt][1],
                ah[cur][mt][2], ah[cur][mt][3], bh[cur][nt][0], bh[cur][nt][1]);
          mma16(acc[mt][nt], ah[cur][mt][0], ah[cur][mt][1],
                ah[cur][mt][2], ah[cur][mt][3], bl[cur][nt][0], bl[cur][nt][1]);
          mma16(acc[mt][nt], al[cur][mt][0], al[cur][mt][1],
                al[cur][mt][2], al[cur][mt][3], bh[cur][nt][0], bh[cur][nt][1]);
        }
      }
    }
    __syncthreads();
    if (c + 3 < KT) fill(s, (c + 3) * 64);
    CP_COMMIT();
  }

#pragma unroll
  for (int mt = 0; mt < 4; mt++) {
#pragma unroll
    for (int nt = 0; nt < 4; nt++) {
      const int row = bm + wm * 64 + mt * 16 + g;
      const int col = bn + wn * 32 + nt * 8 + 2 * t;
      if (MODE == 0) {
        *(float2*)(Cf + (size_t)row * N + col) =
            make_float2(acc[mt][nt][0], acc[mt][nt][1]);
        *(float2*)(Cf + (size_t)(row + 8) * N + col) =
            make_float2(acc[mt][nt][2], acc[mt][nt][3]);
      } else {
        uint16_t h0, l0, h1, l1;
        split1(acc[mt][nt][0], h0, l0); split1(acc[mt][nt][1], h1, l1);
        *(uint32_t*)(Chi + (size_t)row * N + col) = h0 | ((uint32_t)h1 << 16);
        *(uint32_t*)(Clo + (size_t)row * N + col) = l0 | ((uint32_t)l1 << 16);
        split1(acc[mt][nt][2], h0, l0); split1(acc[mt][nt][3], h1, l1);
        *(uint32_t*)(Chi + (size_t)(row + 8) * N + col) = h0 | ((uint32_t)h1 << 16);
        *(uint32_t*)(Clo + (size_t)(row + 8) * N + col) = l0 | ((uint32_t)l1 << 16);
      }
    }
  }
}

// ---------------------------------------------------------------------------
// bf16x3 causal flash attention (R4 version, best measured).
// CTA = 64 queries of one (b,h), 4 warps. P stays in registers.
// SMEM: Qh 8K | Ql 8K | Kh x2 16K | Kl x2 16K | Vh x2 16K | Vl x2 16K = 80KB
// ---------------------------------------------------------------------------
#define AQH 0
#define AQL 8192
#define AKH 16384
#define AKL 32768
#define AVH 49152
#define AVL 65536
#define ASMEM_TOTAL 81920

__global__ __launch_bounds__(128) void attn3(
    const __nv_bfloat16* __restrict__ qh, const __nv_bfloat16* __restrict__ ql,
    __nv_bfloat16* __restrict__ oh, __nv_bfloat16* __restrict__ ol) {
  extern __shared__ char sm[];
  const int qi = blockIdx.x, h = blockIdx.y, b = blockIdx.z;
  const int tid = threadIdx.x, w = tid >> 5, lane = tid & 31;
  const int g = lane >> 2, t = lane & 3;
  const int q0 = qi * 64;
  const int r0 = w * 16 + g;
  const size_t rowQ = (size_t)(b * TT + q0);

  auto fillKV = [&](int kb, int bf) {
    const size_t base = (size_t)(b * TT + kb * 64) * 3 * CM + CM + h * 64;
    char* kh = sm + AKH + bf * 8192;
    char* kl = sm + AKL + bf * 8192;
    char* vh = sm + AVH + bf * 8192;
    char* vl = sm + AVL + bf * 8192;
#pragma unroll
    for (int i = tid; i < 512; i += 128) {
      int row = i >> 3, c = i & 7;
      uint32_t swo = sw128((uint32_t)(row * 128 + c * 16));
      size_t src = base + (size_t)row * 3 * CM + c * 8;
      cp16(smem_u32(kh + swo), qh + src);
      cp16(smem_u32(kl + swo), ql + src);
      cp16(smem_u32(vh + swo), qh + src + CM);
      cp16(smem_u32(vl + swo), ql + src + CM);
    }
  };

  // prologue: Q + KV block 0, one group
#pragma unroll
  for (int i = tid; i < 512; i += 128) {
    int row = i >> 3, c = i & 7;
    uint32_t swo = sw128((uint32_t)(row * 128 + c * 16));
    size_t src = (rowQ + row) * 3 * CM + h * 64 + c * 8;
    cp16(smem_u32(sm + AQH + swo), qh + src);
    cp16(smem_u32(sm + AQL + swo), ql + src);
  }
  fillKV(0, 0);
  CP_COMMIT();

  float m0 = -1e30f, m1 = -1e30f, l0 = 0.f, l1 = 0.f;
  float o[8][4];
#pragma unroll
  for (int j = 0; j < 8; j++)
#pragma unroll
    for (int r = 0; r < 4; r++) o[j][r] = 0.f;

  const uint32_t xg = (uint32_t)g << 4;

  for (int kj = 0; kj <= qi; kj++) {
    const int buf = kj & 1;
    if (kj < qi) fillKV(kj + 1, buf ^ 1);
    CP_COMMIT();
    CP_WAIT(1);
    __syncthreads();

    const char* Kh = sm + AKH + buf * 8192;
    const char* Kl = sm + AKL + buf * 8192;
    const char* Qh = sm + AQH;
    const char* Ql = sm + AQL;
    const uint32_t vhU = smem_u32(sm + AVH + buf * 8192);
    const uint32_t vlU = smem_u32(sm + AVL + buf * 8192);

    // ---- S = Q K^T (3-pass bf16) ----
    float s[8][4];
#pragma unroll
    for (int j = 0; j < 8; j++)
#pragma unroll
      for (int r = 0; r < 4; r++) s[j][r] = 0.f;

#pragma unroll
    for (int kt = 0; kt < 4; kt++) {
      const uint32_t xo = ((uint32_t)(kt * 32 + t * 4)) ^ xg;
      const char* qrh = Qh + r0 * 128;
      const char* qrl = Ql + r0 * 128;
      uint32_t ah0 = ldu(qrh + xo),        ah1 = ldu(qrh + 1024 + xo);
      uint32_t ah2 = ldu(qrh + (xo ^ 16)), ah3 = ldu(qrh + 1024 + (xo ^ 16));
      uint32_t al0 = ldu(qrl + xo),        al1 = ldu(qrl + 1024 + xo);
      uint32_t al2 = ldu(qrl + (xo ^ 16)), al3 = ldu(qrl + 1024 + (xo ^ 16));
#pragma unroll
      for (int j = 0; j < 8; j++) {
        const char* krh = Kh + (j * 8 + g) * 128;
        const char* krl = Kl + (j * 8 + g) * 128;
        uint32_t bh0 = ldu(krh + xo), bh1 = ldu(krh + (xo ^ 16));
        uint32_t bl0 = ldu(krl + xo), bl1 = ldu(krl + (xo ^ 16));
        mma16(s[j], ah0, ah1, ah2, ah3, bh0, bh1);
        mma16(s[j], ah0, ah1, ah2, ah3, bl0, bl1);
        mma16(s[j], al0, al1, al2, al3, bh0, bh1);
      }
    }

    // scale 1/sqrt(64), causal mask on diagonal block
#pragma unroll
    for (int j = 0; j < 8; j++)
#pragma unroll
      for (int r = 0; r < 4; r++) s[j][r] *= 0.125f;

    if (kj == qi) {
#pragma unroll
      for (int j = 0; j < 8; j++) {
        const int c = j * 8 + 2 * t;
        if (c     > r0)     s[j][0] = -1e30f;
        if (c + 1 > r0)     s[j][1] = -1e30f;
        if (c     > r0 + 8) s[j][2] = -1e30f;
        if (c + 1 > r0 + 8) s[j][3] = -1e30f;
      }
    }

    // ---- online softmax (rows r0, r0+8; 4 quad lanes share a row) ----
    float rm0 = -1e30f, rm1 = -1e30f;
#pragma unroll
    for (int j = 0; j < 8; j++) {
      rm0 = fmaxf(rm0, fmaxf(s[j][0], s[j][1]));
      rm1 = fmaxf(rm1, fmaxf(s[j][2], s[j][3]));
    }
    rm0 = fmaxf(rm0, __shfl_xor_sync(0xffffffffu, rm0, 1));
    rm0 = fmaxf(rm0, __shfl_xor_sync(0xffffffffu, rm0, 2));
    rm1 = fmaxf(rm1, __shfl_xor_sync(0xffffffffu, rm1, 1));
    rm1 = fmaxf(rm1, __shfl_xor_sync(0xffffffffu, rm1, 2));
    const float mn0 = fmaxf(m0, rm0), mn1 = fmaxf(m1, rm1);
    const float al_0 = __expf(m0 - mn0), al_1 = __expf(m1 - mn1);
    float rs0 = 0.f, rs1 = 0.f;
#pragma unroll
    for (int j = 0; j < 8; j++) {
      s[j][0] = __expf(s[j][0] - mn0);
      s[j][1] = __expf(s[j][1] - mn0);
      s[j][2] = __expf(s[j][2] - mn1);
      s[j][3] = __expf(s[j][3] - mn1);
      rs0 += s[j][0] + s[j][1];
      rs1 += s[j][2] + s[j][3];
    }
    rs0 += __shfl_xor_sync(0xffffffffu, rs0, 1);
    rs0 += __shfl_xor_sync(0xffffffffu, rs0, 2);
    rs1 += __shfl_xor_sync(0xffffffffu, rs1, 1);
    rs1 += __shfl_xor_sync(0xffffffffu, rs1, 2);
    l0 = l0 * al_0 + rs0;  m0 = mn0;
    l1 = l1 * al_1 + rs1;  m1 = mn1;
#pragma unroll
    for (int j = 0; j < 8; j++) {
      o[j][0] *= al_0; o[j][1] *= al_0;
      o[j][2] *= al_1; o[j][3] *= al_1;
    }

    // ---- split P in registers (accumulator layout == A-frag layout) ----
    uint32_t ph01[8], ph23[8], pl01[8], pl23[8];
#pragma unroll
    for (int j = 0; j < 8; j++) {
      uint16_t h0, l0_, h1, l1_;
      split1(s[j][0], h0, l0_); split1(s[j][1], h1, l1_);
      ph01[j] = h0 | ((uint32_t)h1 << 16);
      pl01[j] = l0_ | ((uint32_t)l1_ << 16);
      split1(s[j][2], h0, l0_); split1(s[j][3], h1, l1_);
      ph23[j] = h0 | ((uint32_t)h1 << 16);
      pl23[j] = l0_ | ((uint32_t)l1_ << 16);
    }

    // ---- O += P V (3-pass; V^T fragments via ldmatrix.x4.trans) ----
    const int qq = lane >> 3, rr = lane & 7;
#pragma unroll
    for (int kt = 0; kt < 4; kt++) {
      const uint32_t pa0 = ph01[2*kt],   pa1 = ph23[2*kt];
      const uint32_t pa2 = ph01[2*kt+1], pa3 = ph23[2*kt+1];
      const uint32_t qa0 = pl01[2*kt],   qa1 = pl23[2*kt];
      const uint32_t qa2 = pl01[2*kt+1], qa3 = pl23[2*kt+1];
      const uint32_t vrow = (uint32_t)(kt * 16 + ((qq & 1) << 3) + rr);
#pragma unroll
      for (int jp = 0; jp < 4; jp++) {
        const uint32_t off = sw128(vrow * 128 + (uint32_t)(jp * 32 + ((qq >> 1) << 4)));
        uint32_t vh0, vh1, vh2, vh3, vl0, vl1, vl2, vl3;
        ldsm4t(vh0, vh1, vh2, vh3, vhU + off);
        ldsm4t(vl0, vl1, vl2, vl3, vlU + off);
        mma16(o[2*jp],     pa0, pa1, pa2, pa3, vh0, vh1);
        mma16(o[2*jp],     pa0, pa1, pa2, pa3, vl0, vl1);
        mma16(o[2*jp],     qa0, qa1, qa2, qa3, vh0, vh1);
        mma16(o[2*jp + 1], pa0, pa1, pa2, pa3, vh2, vh3);
        mma16(o[2*jp + 1], pa0, pa1, pa2, pa3, vl2, vl3);
        mma16(o[2*jp + 1], qa0, qa1, qa2, qa3, vh2, vh3);
      }
    }
    __syncthreads();   // tiles consumed before next prefetch overwrites
  }

  // ---- epilogue: O /= l, split to hi/lo bf16 ----
  const float i0 = 1.f / l0, i1 = 1.f / l1;
  const size_t ro0 = (rowQ + r0) * CM + h * 64;
  const size_t ro1 = ro0 + 8 * (size_t)CM;
#pragma unroll
  for (int j = 0; j < 8; j++) {
    const int col = j * 8 + 2 * t;
    uint16_t h0, l0_, h1, l1_;
    split1(o[j][0] * i0, h0, l0_); split1(o[j][1] * i0, h1, l1_);
    *(uint32_t*)(oh + ro0 + col) = h0 | ((uint32_t)h1 << 16);
    *(uint32_t*)(ol + ro0 + col) = l0_ | ((uint32_t)l1_ << 16);
    split1(o[j][2] * i1, h0, l0_); split1(o[j][3] * i1, h1, l1_);
    *(uint32_t*)(oh + ro1 + col) = h0 | ((uint32_t)h1 << 16);
    *(uint32_t*)(ol + ro1 + col) = l0_ | ((uint32_t)l1_ << 16);
  }
}

// ---------------------------------------------------------------------------
extern "C" void kernel_launch(void* const* d_in, const int* in_sizes, int n_in,
                              void* d_out, int out_size) {
  const float* x     = (const float*)d_in[0];   // [4,2048,1024]
  const float* w_qkv = (const float*)d_in[1];   // [3072,1024]
  const float* w_out = (const float*)d_in[2];   // [1024,1024]
  float* out = (float*)d_out;

  __nv_bfloat16 *xh, *xl, *wqh, *wql, *woh, *wol, *qkvh, *qkvl, *ath, *atl;
  cudaGetSymbolAddress((void**)&xh,  g_x_hi);    cudaGetSymbolAddress((void**)&xl,  g_x_lo);
  cudaGetSymbolAddress((void**)&wqh, g_wqkv_hi); cudaGetSymbolAddress((void**)&wql, g_wqkv_lo);
  cudaGetSymbolAddress((void**)&woh, g_wout_hi); cudaGetSymbolAddress((void**)&wol, g_wout_lo);
  cudaGetSymbolAddress((void**)&qkvh, g_qkv_hi); cudaGetSymbolAddress((void**)&qkvl, g_qkv_lo);
  cudaGetSymbolAddress((void**)&ath, g_att_hi);  cudaGetSymbolAddress((void**)&atl, g_att_lo);

  cudaFuncSetAttribute(gemm3<0>, cudaFuncAttributeMaxDynamicSharedMemorySize, GSMEM_TOTAL);
  cudaFuncSetAttribute(gemm3<1>, cudaFuncAttributeMaxDynamicSharedMemorySize, GSMEM_TOTAL);
  cudaFuncSetAttribute(attn3,    cudaFuncAttributeMaxDynamicSharedMemorySize, ASMEM_TOTAL);

  // 0) split inputs into bf16 hi/lo
  {
    int n4 = MR * CM / 4;
    split_kernel<<<(n4 + 255) / 256, 256>>>(x, xh, xl, n4);
    n4 = 3 * CM * CM / 4;
    split_kernel<<<(n4 + 255) / 256, 256>>>(w_qkv, wqh, wql, n4);
    n4 = CM * CM / 4;
    split_kernel<<<(n4 + 255) / 256, 256>>>(w_out, woh, wol, n4);
  }

  // 1) QKV projection -> qkv hi/lo bf16
  gemm3<1><<<dim3(3*CM/128, MR/128), 256, GSMEM_TOTAL>>>(
      xh, xl, wqh, wql, nullptr, qkvh, qkvl, 3*CM, CM);

  // 2) causal flash attention -> att hi/lo bf16
  attn3<<<dim3(TT/64, HH, BB), 128, ASMEM_TOTAL>>>(qkvh, qkvl, ath, atl);

  // 3) output projection -> fp32 out
  gemm3<0><<<dim3(CM/128, MR/128), 256, GSMEM_TOTAL>>>(
      ath, atl, woh, wol, out, nullptr, nullptr, CM, CM);
}

// round 8
// speedup vs baseline: 1.1954x; 1.1080x over previous
#include <cuda_runtime.h>
#include <cuda_fp16.h>
#include <cstdint>

#define CM 1024
#define TT 2048
#define BB 4
#define HH 16
#define MR (BB*TT)   // 8192 rows

// ---------------------------------------------------------------------------
// Scratch (device globals: allocation-free per harness rules). 16-bit bit
// containers holding fp16 hi/lo split values.
// ---------------------------------------------------------------------------
__device__ __half g_x_hi[(size_t)MR * CM],       g_x_lo[(size_t)MR * CM];
__device__ __half g_wqkv_hi[3 * CM * CM],        g_wqkv_lo[3 * CM * CM];
__device__ __half g_wout_hi[CM * CM],            g_wout_lo[CM * CM];
__device__ __half g_qkv_hi[(size_t)MR * 3 * CM], g_qkv_lo[(size_t)MR * 3 * CM];
__device__ __half g_att_hi[(size_t)MR * CM],     g_att_lo[(size_t)MR * CM];

// ---------------------------------------------------------------------------
// helpers
// ---------------------------------------------------------------------------
__device__ __forceinline__ uint32_t smem_u32(const void* p) {
  uint32_t a;
  asm("{ .reg .u64 t; cvta.to.shared.u64 t, %1; cvt.u32.u64 %0, t; }"
      : "=r"(a) : "l"(p));
  return a;
}
__device__ __forceinline__ void cp16(uint32_t s, const void* g) {
  asm volatile("cp.async.cg.shared.global [%0], [%1], 16;" :: "r"(s), "l"(g));
}
#define CP_COMMIT() asm volatile("cp.async.commit_group;" ::: "memory")
#define CP_WAIT(n)  asm volatile("cp.async.wait_group %0;" :: "n"(n) : "memory")

// D += A*B, m16n8k16 fp16 operands, fp32 accumulate
__device__ __forceinline__ void mma16(float* d, uint32_t a0, uint32_t a1,
                                      uint32_t a2, uint32_t a3,
                                      uint32_t b0, uint32_t b1) {
  asm volatile(
      "mma.sync.aligned.m16n8k16.row.col.f32.f16.f16.f32 "
      "{%0,%1,%2,%3}, {%4,%5,%6,%7}, {%8,%9}, {%0,%1,%2,%3};"
      : "+f"(d[0]), "+f"(d[1]), "+f"(d[2]), "+f"(d[3])
      : "r"(a0), "r"(a1), "r"(a2), "r"(a3), "r"(b0), "r"(b1));
}
__device__ __forceinline__ void ldsm4t(uint32_t& r0, uint32_t& r1,
                                       uint32_t& r2, uint32_t& r3, uint32_t a) {
  asm volatile("ldmatrix.sync.aligned.m8n8.x4.trans.shared.b16 "
               "{%0,%1,%2,%3}, [%4];"
               : "=r"(r0), "=r"(r1), "=r"(r2), "=r"(r3) : "r"(a));
}
__device__ __forceinline__ uint32_t ldu(const void* p) {
  return *(const uint32_t*)p;
}
__device__ __forceinline__ uint32_t sw128(uint32_t o) { return o ^ ((o >> 3) & 0x70); }

// split fp32 -> fp16 hi + fp16 lo (x = hi + lo + O(2^-23 x))
__device__ __forceinline__ void split1(float x, uint16_t& h, uint16_t& l) {
  __half hh = __float2half_rn(x);
  float r = x - __half2float(hh);
  __half hl = __float2half_rn(r);
  h = __half_as_ushort(hh);
  l = __half_as_ushort(hl);
}
__device__ __forceinline__ uint32_t pack_h2(float a, float b) {
  __half2 p = __floats2half2_rn(a, b);
  return *(uint32_t*)&p;
}

// ---------------------------------------------------------------------------
// elementwise split: fp32 -> (hi, lo) fp16
// ---------------------------------------------------------------------------
__global__ __launch_bounds__(256) void split_kernel(
    const float* __restrict__ in, __half* __restrict__ hi,
    __half* __restrict__ lo, int n4) {
  int i = blockIdx.x * blockDim.x + threadIdx.x;
  if (i >= n4) return;
  float4 v = ((const float4*)in)[i];
  uint16_t h0, h1, h2, h3, l0, l1, l2, l3;
  split1(v.x, h0, l0); split1(v.y, h1, l1);
  split1(v.z, h2, l2); split1(v.w, h3, l3);
  ((uint2*)hi)[i] = make_uint2(h0 | ((uint32_t)h1 << 16), h2 | ((uint32_t)h3 << 16));
  ((uint2*)lo)[i] = make_uint2(l0 | ((uint32_t)l1 << 16), l2 | ((uint32_t)l3 << 16));
}

// ---------------------------------------------------------------------------
// fp16x3 TN GEMM: C[M,N] = A[M,K] * B[N,K]^T, A/B given as fp16 hi/lo pairs.
// CTA 128x128, BK=64, 3-stage cp.async, 256 threads (8 warps: 2x4, 64x32 each)
// Register double-buffered fragments (R7 structure, best measured).
// MODE 0: write fp32 C.  MODE 1: write fp16 hi/lo C.
// ---------------------------------------------------------------------------
#define GSMEM_TOTAL (3 * 65536)

template<int MODE>
__global__ __launch_bounds__(256) void gemm3(
    const __half* __restrict__ Ah_, const __half* __restrict__ Al_,
    const __half* __restrict__ Bh_, const __half* __restrict__ Bl_,
    float* __restrict__ Cf, __half* __restrict__ Chi,
    __half* __restrict__ Clo, int N, int K) {
  extern __shared__ char sm[];
  const int tid = threadIdx.x, w = tid >> 5, lane = tid & 31;
  const int g = lane >> 2, t = lane & 3;
  const int wm = w & 1, wn = w >> 1;
  const int bm = blockIdx.y * 128, bn = blockIdx.x * 128;

  float acc[4][4][4];
#pragma unroll
  for (int mt = 0; mt < 4; mt++)
#pragma unroll
    for (int nt = 0; nt < 4; nt++)
#pragma unroll
      for (int r = 0; r < 4; r++) acc[mt][nt][r] = 0.f;

  // stage: Ah | Al | Bh | Bl, each 128 rows x 128B (64 fp16), SW128 swizzled
  auto fill = [&](int s, int k0) {
    char* base = sm + s * 65536;
#pragma unroll
    for (int i = tid; i < 1024; i += 256) {
      int row = i >> 3, c = i & 7;
      uint32_t swo = sw128((uint32_t)(row * 128 + c * 16));
      size_t ao = (size_t)(bm + row) * K + k0 + c * 8;
      size_t bo = (size_t)(bn + row) * K + k0 + c * 8;
      cp16(smem_u32(base + swo),         Ah_ + ao);
      cp16(smem_u32(base + 16384 + swo), Al_ + ao);
      cp16(smem_u32(base + 32768 + swo), Bh_ + bo);
      cp16(smem_u32(base + 49152 + swo), Bl_ + bo);
    }
  };

  const int KT = K >> 6;
  fill(0, 0);   CP_COMMIT();
  fill(1, 64);  CP_COMMIT();
  fill(2, 128); CP_COMMIT();

  const uint32_t xg = (uint32_t)g << 4;

  for (int c = 0; c < KT; c++) {
    const int s = c - (c / 3) * 3;
    CP_WAIT(2);
    __syncthreads();
    const char* Ah = sm + s * 65536;
    const char* Al = Ah + 16384;
    const char* Bh = Ah + 32768;
    const char* Bl = Ah + 49152;

    // fragment register double-buffers
    uint32_t ah[2][4][4], al[2][4][4], bh[2][4][2], bl[2][4][2];

    auto loadFrags = [&](int kt, int buf) {
      const uint32_t xo = ((uint32_t)(kt * 32 + t * 4)) ^ xg;
#pragma unroll
      for (int mt = 0; mt < 4; mt++) {
        const char* ar  = Ah + (wm * 64 + mt * 16 + g) * 128;
        const char* arl = Al + (wm * 64 + mt * 16 + g) * 128;
        ah[buf][mt][0] = ldu(ar + xo);
        ah[buf][mt][1] = ldu(ar + 1024 + xo);
        ah[buf][mt][2] = ldu(ar + (xo ^ 16));
        ah[buf][mt][3] = ldu(ar + 1024 + (xo ^ 16));
        al[buf][mt][0] = ldu(arl + xo);
        al[buf][mt][1] = ldu(arl + 1024 + xo);
        al[buf][mt][2] = ldu(arl + (xo ^ 16));
        al[buf][mt][3] = ldu(arl + 1024 + (xo ^ 16));
      }
#pragma unroll
      for (int nt = 0; nt < 4; nt++) {
        const char* br  = Bh + (wn * 32 + nt * 8 + g) * 128;
        const char* brl = Bl + (wn * 32 + nt * 8 + g) * 128;
        bh[buf][nt][0] = ldu(br + xo);
        bh[buf][nt][1] = ldu(br + (xo ^ 16));
        bl[buf][nt][0] = ldu(brl + xo);
        bl[buf][nt][1] = ldu(brl + (xo ^ 16));
      }
    };

    loadFrags(0, 0);
#pragma unroll
    for (int kt = 0; kt < 4; kt++) {
      const int cur = kt & 1;
      if (kt < 3) loadFrags(kt + 1, cur ^ 1);   // prefetch next kt's fragments
#pragma unroll
      for (int nt = 0; nt < 4; nt++) {
#pragma unroll
        for (int mt = 0; mt < 4; mt++) {
          mma16(acc[mt][nt], ah[cur][mt][0], ah[cur][mt][1],
                ah[cur][mt][2], ah[cur][mt][3], bh[cur][nt][0], bh[cur][nt][1]);
          mma16(acc[mt][nt], ah[cur][mt][0], ah[cur][mt][1],
                ah[cur][mt][2], ah[cur][mt][3], bl[cur][nt][0], bl[cur][nt][1]);
          mma16(acc[mt][nt], al[cur][mt][0], al[cur][mt][1],
                al[cur][mt][2], al[cur][mt][3], bh[cur][nt][0], bh[cur][nt][1]);
        }
      }
    }
    __syncthreads();
    if (c + 3 < KT) fill(s, (c + 3) * 64);
    CP_COMMIT();
  }

#pragma unroll
  for (int mt = 0; mt < 4; mt++) {
#pragma unroll
    for (int nt = 0; nt < 4; nt++) {
      const int row = bm + wm * 64 + mt * 16 + g;
      const int col = bn + wn * 32 + nt * 8 + 2 * t;
      if (MODE == 0) {
        *(float2*)(Cf + (size_t)row * N + col) =
            make_float2(acc[mt][nt][0], acc[mt][nt][1]);
        *(float2*)(Cf + (size_t)(row + 8) * N + col) =
            make_float2(acc[mt][nt][2], acc[mt][nt][3]);
      } else {
        uint16_t h0, l0, h1, l1;
        split1(acc[mt][nt][0], h0, l0); split1(acc[mt][nt][1], h1, l1);
        *(uint32_t*)(Chi + (size_t)row * N + col) = h0 | ((uint32_t)h1 << 16);
        *(uint32_t*)(Clo + (size_t)row * N + col) = l0 | ((uint32_t)l1 << 16);
        split1(acc[mt][nt][2], h0, l0); split1(acc[mt][nt][3], h1, l1);
        *(uint32_t*)(Chi + (size_t)(row + 8) * N + col) = h0 | ((uint32_t)h1 << 16);
        *(uint32_t*)(Clo + (size_t)(row + 8) * N + col) = l0 | ((uint32_t)l1 << 16);
      }
    }
  }
}

// ---------------------------------------------------------------------------
// fp16 causal flash attention, 2-pass per matmul:
//   S  = Qh*Kh^T + Qh*Kl^T      (Ql dropped: 2^-12 relative)
//   O += Ph*Vh   + Ph*Vl        (Pl dropped: 2^-12 relative)
// CTA = 64 queries of one (b,h), 4 warps. P stays in registers.
// SMEM: Qh 8K | Ql 8K | Kh x2 16K | Kl x2 16K | Vh x2 16K | Vl x2 16K = 80KB
// ---------------------------------------------------------------------------
#define AQH 0
#define AQL 8192
#define AKH 16384
#define AKL 32768
#define AVH 49152
#define AVL 65536
#define ASMEM_TOTAL 81920

__global__ __launch_bounds__(128) void attn3(
    const __half* __restrict__ qh, const __half* __restrict__ ql,
    __half* __restrict__ oh, __half* __restrict__ ol) {
  extern __shared__ char sm[];
  const int qi = blockIdx.x, h = blockIdx.y, b = blockIdx.z;
  const int tid = threadIdx.x, w = tid >> 5, lane = tid & 31;
  const int g = lane >> 2, t = lane & 3;
  const int q0 = qi * 64;
  const int r0 = w * 16 + g;
  const size_t rowQ = (size_t)(b * TT + q0);

  auto fillKV = [&](int kb, int bf) {
    const size_t base = (size_t)(b * TT + kb * 64) * 3 * CM + CM + h * 64;
    char* kh = sm + AKH + bf * 8192;
    char* kl = sm + AKL + bf * 8192;
    char* vh = sm + AVH + bf * 8192;
    char* vl = sm + AVL + bf * 8192;
#pragma unroll
    for (int i = tid; i < 512; i += 128) {
      int row = i >> 3, c = i & 7;
      uint32_t swo = sw128((uint32_t)(row * 128 + c * 16));
      size_t src = base + (size_t)row * 3 * CM + c * 8;
      cp16(smem_u32(kh + swo), qh + src);
      cp16(smem_u32(kl + swo), ql + src);
      cp16(smem_u32(vh + swo), qh + src + CM);
      cp16(smem_u32(vl + swo), ql + src + CM);
    }
  };

  // prologue: Q + KV block 0, one group
#pragma unroll
  for (int i = tid; i < 512; i += 128) {
    int row = i >> 3, c = i & 7;
    uint32_t swo = sw128((uint32_t)(row * 128 + c * 16));
    size_t src = (rowQ + row) * 3 * CM + h * 64 + c * 8;
    cp16(smem_u32(sm + AQH + swo), qh + src);
    cp16(smem_u32(sm + AQL + swo), ql + src);
  }
  fillKV(0, 0);
  CP_COMMIT();

  float m0 = -1e30f, m1 = -1e30f, l0 = 0.f, l1 = 0.f;
  float o[8][4];
#pragma unroll
  for (int j = 0; j < 8; j++)
#pragma unroll
    for (int r = 0; r < 4; r++) o[j][r] = 0.f;

  const uint32_t xg = (uint32_t)g << 4;

  for (int kj = 0; kj <= qi; kj++) {
    const int buf = kj & 1;
    if (kj < qi) fillKV(kj + 1, buf ^ 1);
    CP_COMMIT();
    CP_WAIT(1);
    __syncthreads();

    const char* Kh = sm + AKH + buf * 8192;
    const char* Kl = sm + AKL + buf * 8192;
    const char* Qh = sm + AQH;
    const uint32_t vhU = smem_u32(sm + AVH + buf * 8192);
    const uint32_t vlU = smem_u32(sm + AVL + buf * 8192);

    // ---- S = Qh K^T (2-pass fp16: Kh then Kl) ----
    float s[8][4];
#pragma unroll
    for (int j = 0; j < 8; j++)
#pragma unroll
      for (int r = 0; r < 4; r++) s[j][r] = 0.f;

#pragma unroll
    for (int kt = 0; kt < 4; kt++) {
      const uint32_t xo = ((uint32_t)(kt * 32 + t * 4)) ^ xg;
      const char* qrh = Qh + r0 * 128;
      uint32_t ah0 = ldu(qrh + xo),        ah1 = ldu(qrh + 1024 + xo);
      uint32_t ah2 = ldu(qrh + (xo ^ 16)), ah3 = ldu(qrh + 1024 + (xo ^ 16));
#pragma unroll
      for (int j = 0; j < 8; j++) {
        const char* krh = Kh + (j * 8 + g) * 128;
        const char* krl = Kl + (j * 8 + g) * 128;
        uint32_t bh0 = ldu(krh + xo), bh1 = ldu(krh + (xo ^ 16));
        uint32_t bl0 = ldu(krl + xo), bl1 = ldu(krl + (xo ^ 16));
        mma16(s[j], ah0, ah1, ah2, ah3, bh0, bh1);
        mma16(s[j], ah0, ah1, ah2, ah3, bl0, bl1);
      }
    }

    // scale 1/sqrt(64), causal mask on diagonal block
#pragma unroll
    for (int j = 0; j < 8; j++)
#pragma unroll
      for (int r = 0; r < 4; r++) s[j][r] *= 0.125f;

    if (kj == qi) {
#pragma unroll
      for (int j = 0; j < 8; j++) {
        const int c = j * 8 + 2 * t;
        if (c     > r0)     s[j][0] = -1e30f;
        if (c + 1 > r0)     s[j][1] = -1e30f;
        if (c     > r0 + 8) s[j][2] = -1e30f;
        if (c + 1 > r0 + 8) s[j][3] = -1e30f;
      }
    }

    // ---- online softmax (rows r0, r0+8; 4 quad lanes share a row) ----
    float rm0 = -1e30f, rm1 = -1e30f;
#pragma unroll
    for (int j = 0; j < 8; j++) {
      rm0 = fmaxf(rm0, fmaxf(s[j][0], s[j][1]));
      rm1 = fmaxf(rm1, fmaxf(s[j][2], s[j][3]));
    }
    rm0 = fmaxf(rm0, __shfl_xor_sync(0xffffffffu, rm0, 1));
    rm0 = fmaxf(rm0, __shfl_xor_sync(0xffffffffu, rm0, 2));
    rm1 = fmaxf(rm1, __shfl_xor_sync(0xffffffffu, rm1, 1));
    rm1 = fmaxf(rm1, __shfl_xor_sync(0xffffffffu, rm1, 2));
    const float mn0 = fmaxf(m0, rm0), mn1 = fmaxf(m1, rm1);
    const float al_0 = __expf(m0 - mn0), al_1 = __expf(m1 - mn1);
    float rs0 = 0.f, rs1 = 0.f;
#pragma unroll
    for (int j = 0; j < 8; j++) {
      s[j][0] = __expf(s[j][0] - mn0);
      s[j][1] = __expf(s[j][1] - mn0);
      s[j][2] = __expf(s[j][2] - mn1);
      s[j][3] = __expf(s[j][3] - mn1);
      rs0 += s[j][0] + s[j][1];
      rs1 += s[j][2] + s[j][3];
    }
    rs0 += __shfl_xor_sync(0xffffffffu, rs0, 1);
    rs0 += __shfl_xor_sync(0xffffffffu, rs0, 2);
    rs1 += __shfl_xor_sync(0xffffffffu, rs1, 1);
    rs1 += __shfl_xor_sync(0xffffffffu, rs1, 2);
    l0 = l0 * al_0 + rs0;  m0 = mn0;
    l1 = l1 * al_1 + rs1;  m1 = mn1;
#pragma unroll
    for (int j = 0; j < 8; j++) {
      o[j][0] *= al_0; o[j][1] *= al_0;
      o[j][2] *= al_1; o[j][3] *= al_1;
    }

    // ---- P -> fp16 hi only, in registers (acc layout == A-frag layout) ----
    uint32_t ph01[8], ph23[8];
#pragma unroll
    for (int j = 0; j < 8; j++) {
      ph01[j] = pack_h2(s[j][0], s[j][1]);
      ph23[j] = pack_h2(s[j][2], s[j][3]);
    }

    // ---- O += Ph V (2-pass: Vh then Vl; V^T via ldmatrix.x4.trans) ----
    const int qq = lane >> 3, rr = lane & 7;
#pragma unroll
    for (int kt = 0; kt < 4; kt++) {
      const uint32_t pa0 = ph01[2*kt],   pa1 = ph23[2*kt];
      const uint32_t pa2 = ph01[2*kt+1], pa3 = ph23[2*kt+1];
      const uint32_t vrow = (uint32_t)(kt * 16 + ((qq & 1) << 3) + rr);
#pragma unroll
      for (int jp = 0; jp < 4; jp++) {
        const uint32_t off = sw128(vrow * 128 + (uint32_t)(jp * 32 + ((qq >> 1) << 4)));
        uint32_t vh0, vh1, vh2, vh3, vl0, vl1, vl2, vl3;
        ldsm4t(vh0, vh1, vh2, vh3, vhU + off);
        ldsm4t(vl0, vl1, vl2, vl3, vlU + off);
        mma16(o[2*jp],     pa0, pa1, pa2, pa3, vh0, vh1);
        mma16(o[2*jp],     pa0, pa1, pa2, pa3, vl0, vl1);
        mma16(o[2*jp + 1], pa0, pa1, pa2, pa3, vh2, vh3);
        mma16(o[2*jp + 1], pa0, pa1, pa2, pa3, vl2, vl3);
      }
    }
    __syncthreads();   // tiles consumed before next prefetch overwrites
  }

  // ---- epilogue: O /= l, split to hi/lo fp16 ----
  const float i0 = 1.f / l0, i1 = 1.f / l1;
  const size_t ro0 = (rowQ + r0) * CM + h * 64;
  const size_t ro1 = ro0 + 8 * (size_t)CM;
#pragma unroll
  for (int j = 0; j < 8; j++) {
    const int col = j * 8 + 2 * t;
    uint16_t h0, l0_, h1, l1_;
    split1(o[j][0] * i0, h0, l0_); split1(o[j][1] * i0, h1, l1_);
    *(uint32_t*)(oh + ro0 + col) = h0 | ((uint32_t)h1 << 16);
    *(uint32_t*)(ol + ro0 + col) = l0_ | ((uint32_t)l1_ << 16);
    split1(o[j][2] * i1, h0, l0_); split1(o[j][3] * i1, h1, l1_);
    *(uint32_t*)(oh + ro1 + col) = h0 | ((uint32_t)h1 << 16);
    *(uint32_t*)(ol + ro1 + col) = l0_ | ((uint32_t)l1_ << 16);
  }
}

// ---------------------------------------------------------------------------
extern "C" void kernel_launch(void* const* d_in, const int* in_sizes, int n_in,
                              void* d_out, int out_size) {
  const float* x     = (const float*)d_in[0];   // [4,2048,1024]
  const float* w_qkv = (const float*)d_in[1];   // [3072,1024]
  const float* w_out = (const float*)d_in[2];   // [1024,1024]
  float* out = (float*)d_out;

  __half *xh, *xl, *wqh, *wql, *woh, *wol, *qkvh, *qkvl, *ath, *atl;
  cudaGetSymbolAddress((void**)&xh,  g_x_hi);    cudaGetSymbolAddress((void**)&xl,  g_x_lo);
  cudaGetSymbolAddress((void**)&wqh, g_wqkv_hi); cudaGetSymbolAddress((void**)&wql, g_wqkv_lo);
  cudaGetSymbolAddress((void**)&woh, g_wout_hi); cudaGetSymbolAddress((void**)&wol, g_wout_lo);
  cudaGetSymbolAddress((void**)&qkvh, g_qkv_hi); cudaGetSymbolAddress((void**)&qkvl, g_qkv_lo);
  cudaGetSymbolAddress((void**)&ath, g_att_hi);  cudaGetSymbolAddress((void**)&atl, g_att_lo);

  cudaFuncSetAttribute(gemm3<0>, cudaFuncAttributeMaxDynamicSharedMemorySize, GSMEM_TOTAL);
  cudaFuncSetAttribute(gemm3<1>, cudaFuncAttributeMaxDynamicSharedMemorySize, GSMEM_TOTAL);
  cudaFuncSetAttribute(attn3,    cudaFuncAttributeMaxDynamicSharedMemorySize, ASMEM_TOTAL);

  // 0) split inputs into fp16 hi/lo
  {
    int n4 = MR * CM / 4;
    split_kernel<<<(n4 + 255) / 256, 256>>>(x, xh, xl, n4);
    n4 = 3 * CM * CM / 4;
    split_kernel<<<(n4 + 255) / 256, 256>>>(w_qkv, wqh, wql, n4);
    n4 = CM * CM / 4;
    split_kernel<<<(n4 + 255) / 256, 256>>>(w_out, woh, wol, n4);
  }

  // 1) QKV projection -> qkv hi/lo fp16 (3-pass)
  gemm3<1><<<dim3(3*CM/128, MR/128), 256, GSMEM_TOTAL>>>(
      xh, xl, wqh, wql, nullptr, qkvh, qkvl, 3*CM, CM);

  // 2) causal flash attention -> att hi/lo fp16 (2-pass S, 2-pass PV)
  attn3<<<dim3(TT/64, HH, BB), 128, ASMEM_TOTAL>>>(qkvh, qkvl, ath, atl);

  // 3) output projection -> fp32 out (3-pass)
  gemm3<0><<<dim3(CM/128, MR/128), 256, GSMEM_TOTAL>>>(
      ath, atl, woh, wol, out, nullptr, nullptr, CM, CM);
}

// round 9
// speedup vs baseline: 1.4829x; 1.2405x over previous
#include <cuda_runtime.h>
#include <cuda_fp16.h>
#include <cstdint>

#define CM 1024
#define TT 2048
#define BB 4
#define HH 16
#define MR (BB*TT)   // 8192 rows

// ---------------------------------------------------------------------------
// Scratch (device globals: allocation-free per harness rules). fp16 hi/lo.
// ---------------------------------------------------------------------------
__device__ __half g_x_hi[(size_t)MR * CM],       g_x_lo[(size_t)MR * CM];
__device__ __half g_wqkv_hi[3 * CM * CM],        g_wqkv_lo[3 * CM * CM];
__device__ __half g_wout_hi[CM * CM],            g_wout_lo[CM * CM];
__device__ __half g_qkv_hi[(size_t)MR * 3 * CM], g_qkv_lo[(size_t)MR * 3 * CM];
__device__ __half g_att_hi[(size_t)MR * CM];

// ---------------------------------------------------------------------------
// helpers
// ---------------------------------------------------------------------------
__device__ __forceinline__ uint32_t smem_u32(const void* p) {
  uint32_t a;
  asm("{ .reg .u64 t; cvta.to.shared.u64 t, %1; cvt.u32.u64 %0, t; }"
      : "=r"(a) : "l"(p));
  return a;
}
__device__ __forceinline__ void cp16(uint32_t s, const void* g) {
  asm volatile("cp.async.cg.shared.global [%0], [%1], 16;" :: "r"(s), "l"(g));
}
#define CP_COMMIT() asm volatile("cp.async.commit_group;" ::: "memory")
#define CP_WAIT(n)  asm volatile("cp.async.wait_group %0;" :: "n"(n) : "memory")

// D += A*B, m16n8k16 fp16 operands, fp32 accumulate
__device__ __forceinline__ void mma16(float* d, uint32_t a0, uint32_t a1,
                                      uint32_t a2, uint32_t a3,
                                      uint32_t b0, uint32_t b1) {
  asm volatile(
      "mma.sync.aligned.m16n8k16.row.col.f32.f16.f16.f32 "
      "{%0,%1,%2,%3}, {%4,%5,%6,%7}, {%8,%9}, {%0,%1,%2,%3};"
      : "+f"(d[0]), "+f"(d[1]), "+f"(d[2]), "+f"(d[3])
      : "r"(a0), "r"(a1), "r"(a2), "r"(a3), "r"(b0), "r"(b1));
}
__device__ __forceinline__ void ldsm4t(uint32_t& r0, uint32_t& r1,
                                       uint32_t& r2, uint32_t& r3, uint32_t a) {
  asm volatile("ldmatrix.sync.aligned.m8n8.x4.trans.shared.b16 "
               "{%0,%1,%2,%3}, [%4];"
               : "=r"(r0), "=r"(r1), "=r"(r2), "=r"(r3) : "r"(a));
}
__device__ __forceinline__ uint32_t ldu(const void* p) {
  return *(const uint32_t*)p;
}
__device__ __forceinline__ uint32_t sw128(uint32_t o) { return o ^ ((o >> 3) & 0x70); }

// split fp32 -> fp16 hi + fp16 lo
__device__ __forceinline__ void split1(float x, uint16_t& h, uint16_t& l) {
  __half hh = __float2half_rn(x);
  float r = x - __half2float(hh);
  __half hl = __float2half_rn(r);
  h = __half_as_ushort(hh);
  l = __half_as_ushort(hl);
}
__device__ __forceinline__ uint32_t pack_h2(float a, float b) {
  __half2 p = __floats2half2_rn(a, b);
  return *(uint32_t*)&p;
}

// ---------------------------------------------------------------------------
// elementwise split: fp32 -> (hi, lo) fp16
// ---------------------------------------------------------------------------
__global__ __launch_bounds__(256) void split_kernel(
    const float* __restrict__ in, __half* __restrict__ hi,
    __half* __restrict__ lo, int n4) {
  int i = blockIdx.x * blockDim.x + threadIdx.x;
  if (i >= n4) return;
  float4 v = ((const float4*)in)[i];
  uint16_t h0, h1, h2, h3, l0, l1, l2, l3;
  split1(v.x, h0, l0); split1(v.y, h1, l1);
  split1(v.z, h2, l2); split1(v.w, h3, l3);
  ((uint2*)hi)[i] = make_uint2(h0 | ((uint32_t)h1 << 16), h2 | ((uint32_t)h3 << 16));
  ((uint2*)lo)[i] = make_uint2(l0 | ((uint32_t)l1 << 16), l2 | ((uint32_t)l3 << 16));
}

// ---------------------------------------------------------------------------
// fp16 2-pass TN GEMM: C[M,N] ~= Ah*(Bh+Bl)^T  (Al*Bh term dropped, ~2^-12)
// CTA 128x128, BK=64, 3-stage cp.async, 256 threads (8 warps: 2x4, 64x32 each)
// Register double-buffered fragments (R7 structure, best measured).
// MODE 0: write fp32 C.  MODE 1: write fp16 hi/lo C.
// ---------------------------------------------------------------------------
#define GSTAGE 49152                     // Ah 16K | Bh 16K | Bl 16K
#define GSMEM_TOTAL (3 * GSTAGE)         // 144 KB

template<int MODE>
__global__ __launch_bounds__(256) void gemm2(
    const __half* __restrict__ Ah_,
    const __half* __restrict__ Bh_, const __half* __restrict__ Bl_,
    float* __restrict__ Cf, __half* __restrict__ Chi,
    __half* __restrict__ Clo, int N, int K) {
  extern __shared__ char sm[];
  const int tid = threadIdx.x, w = tid >> 5, lane = tid & 31;
  const int g = lane >> 2, t = lane & 3;
  const int wm = w & 1, wn = w >> 1;
  const int bm = blockIdx.y * 128, bn = blockIdx.x * 128;

  float acc[4][4][4];
#pragma unroll
  for (int mt = 0; mt < 4; mt++)
#pragma unroll
    for (int nt = 0; nt < 4; nt++)
#pragma unroll
      for (int r = 0; r < 4; r++) acc[mt][nt][r] = 0.f;

  // stage: Ah | Bh | Bl, each 128 rows x 128B (64 fp16), SW128 swizzled
  auto fill = [&](int s, int k0) {
    char* base = sm + s * GSTAGE;
#pragma unroll
    for (int i = tid; i < 3072; i += 256) {
      int buf = i >> 10;            // 0=Ah, 1=Bh, 2=Bl
      int row = (i >> 3) & 127;
      int c = i & 7;
      uint32_t swo = sw128((uint32_t)(row * 128 + c * 16));
      size_t off = (size_t)((buf ? bn : bm) + row) * K + k0 + c * 8;
      const __half* src = (buf == 0) ? Ah_ + off
                        : (buf == 1) ? Bh_ + off : Bl_ + off;
      cp16(smem_u32(base + buf * 16384 + swo), src);
    }
  };

  const int KT = K >> 6;
  fill(0, 0);   CP_COMMIT();
  fill(1, 64);  CP_COMMIT();
  fill(2, 128); CP_COMMIT();

  const uint32_t xg = (uint32_t)g << 4;

  for (int c = 0; c < KT; c++) {
    const int s = c - (c / 3) * 3;
    CP_WAIT(2);
    __syncthreads();
    const char* Ah = sm + s * GSTAGE;
    const char* Bh = Ah + 16384;
    const char* Bl = Ah + 32768;

    // fragment register double-buffers
    uint32_t ah[2][4][4], bh[2][4][2], bl[2][4][2];

    auto loadFrags = [&](int kt, int buf) {
      const uint32_t xo = ((uint32_t)(kt * 32 + t * 4)) ^ xg;
#pragma unroll
      for (int mt = 0; mt < 4; mt++) {
        const char* ar = Ah + (wm * 64 + mt * 16 + g) * 128;
        ah[buf][mt][0] = ldu(ar + xo);
        ah[buf][mt][1] = ldu(ar + 1024 + xo);
        ah[buf][mt][2] = ldu(ar + (xo ^ 16));
        ah[buf][mt][3] = ldu(ar + 1024 + (xo ^ 16));
      }
#pragma unroll
      for (int nt = 0; nt < 4; nt++) {
        const char* br  = Bh + (wn * 32 + nt * 8 + g) * 128;
        const char* brl = Bl + (wn * 32 + nt * 8 + g) * 128;
        bh[buf][nt][0] = ldu(br + xo);
        bh[buf][nt][1] = ldu(br + (xo ^ 16));
        bl[buf][nt][0] = ldu(brl + xo);
        bl[buf][nt][1] = ldu(brl + (xo ^ 16));
      }
    };

    loadFrags(0, 0);
#pragma unroll
    for (int kt = 0; kt < 4; kt++) {
      const int cur = kt & 1;
      if (kt < 3) loadFrags(kt + 1, cur ^ 1);   // prefetch next kt's fragments
#pragma unroll
      for (int nt = 0; nt < 4; nt++) {
#pragma unroll
        for (int mt = 0; mt < 4; mt++) {
          mma16(acc[mt][nt], ah[cur][mt][0], ah[cur][mt][1],
                ah[cur][mt][2], ah[cur][mt][3], bh[cur][nt][0], bh[cur][nt][1]);
          mma16(acc[mt][nt], ah[cur][mt][0], ah[cur][mt][1],
                ah[cur][mt][2], ah[cur][mt][3], bl[cur][nt][0], bl[cur][nt][1]);
        }
      }
    }
    __syncthreads();
    if (c + 3 < KT) fill(s, (c + 3) * 64);
    CP_COMMIT();
  }

#pragma unroll
  for (int mt = 0; mt < 4; mt++) {
#pragma unroll
    for (int nt = 0; nt < 4; nt++) {
      const int row = bm + wm * 64 + mt * 16 + g;
      const int col = bn + wn * 32 + nt * 8 + 2 * t;
      if (MODE == 0) {
        *(float2*)(Cf + (size_t)row * N + col) =
            make_float2(acc[mt][nt][0], acc[mt][nt][1]);
        *(float2*)(Cf + (size_t)(row + 8) * N + col) =
            make_float2(acc[mt][nt][2], acc[mt][nt][3]);
      } else {
        uint16_t h0, l0, h1, l1;
        split1(acc[mt][nt][0], h0, l0); split1(acc[mt][nt][1], h1, l1);
        *(uint32_t*)(Chi + (size_t)row * N + col) = h0 | ((uint32_t)h1 << 16);
        *(uint32_t*)(Clo + (size_t)row * N + col) = l0 | ((uint32_t)l1 << 16);
        split1(acc[mt][nt][2], h0, l0); split1(acc[mt][nt][3], h1, l1);
        *(uint32_t*)(Chi + (size_t)(row + 8) * N + col) = h0 | ((uint32_t)h1 << 16);
        *(uint32_t*)(Clo + (size_t)(row + 8) * N + col) = l0 | ((uint32_t)l1 << 16);
      }
    }
  }
}

// ---------------------------------------------------------------------------
// fp16 causal flash attention, 2-pass per matmul (R8 structure):
//   S  = Qh*Kh^T + Qh*Kl^T      (Ql dropped)
//   O += Ph*Vh   + Ph*Vl        (Pl dropped)
// Output: hi fp16 only (projection drops its A-lo pass).
// SMEM: Qh 8K | Kh x2 16K | Kl x2 16K | Vh x2 16K | Vl x2 16K = 72KB
// ---------------------------------------------------------------------------
#define AQH 0
#define AKH 8192
#define AKL 24576
#define AVH 40960
#define AVL 57344
#define ASMEM_TOTAL 73728

__global__ __launch_bounds__(128) void attn2(
    const __half* __restrict__ qh, const __half* __restrict__ ql,
    __half* __restrict__ oh) {
  extern __shared__ char sm[];
  const int qi = blockIdx.x, h = blockIdx.y, b = blockIdx.z;
  const int tid = threadIdx.x, w = tid >> 5, lane = tid & 31;
  const int g = lane >> 2, t = lane & 3;
  const int q0 = qi * 64;
  const int r0 = w * 16 + g;
  const size_t rowQ = (size_t)(b * TT + q0);

  auto fillKV = [&](int kb, int bf) {
    const size_t base = (size_t)(b * TT + kb * 64) * 3 * CM + CM + h * 64;
    char* kh = sm + AKH + bf * 8192;
    char* kl = sm + AKL + bf * 8192;
    char* vh = sm + AVH + bf * 8192;
    char* vl = sm + AVL + bf * 8192;
#pragma unroll
    for (int i = tid; i < 512; i += 128) {
      int row = i >> 3, c = i & 7;
      uint32_t swo = sw128((uint32_t)(row * 128 + c * 16));
      size_t src = base + (size_t)row * 3 * CM + c * 8;
      cp16(smem_u32(kh + swo), qh + src);
      cp16(smem_u32(kl + swo), ql + src);
      cp16(smem_u32(vh + swo), qh + src + CM);
      cp16(smem_u32(vl + swo), ql + src + CM);
    }
  };

  // prologue: Qh + KV block 0, one group
#pragma unroll
  for (int i = tid; i < 512; i += 128) {
    int row = i >> 3, c = i & 7;
    uint32_t swo = sw128((uint32_t)(row * 128 + c * 16));
    size_t src = (rowQ + row) * 3 * CM + h * 64 + c * 8;
    cp16(smem_u32(sm + AQH + swo), qh + src);
  }
  fillKV(0, 0);
  CP_COMMIT();

  float m0 = -1e30f, m1 = -1e30f, l0 = 0.f, l1 = 0.f;
  float o[8][4];
#pragma unroll
  for (int j = 0; j < 8; j++)
#pragma unroll
    for (int r = 0; r < 4; r++) o[j][r] = 0.f;

  const uint32_t xg = (uint32_t)g << 4;

  for (int kj = 0; kj <= qi; kj++) {
    const int buf = kj & 1;
    if (kj < qi) fillKV(kj + 1, buf ^ 1);
    CP_COMMIT();
    CP_WAIT(1);
    __syncthreads();

    const char* Kh = sm + AKH + buf * 8192;
    const char* Kl = sm + AKL + buf * 8192;
    const char* Qh = sm + AQH;
    const uint32_t vhU = smem_u32(sm + AVH + buf * 8192);
    const uint32_t vlU = smem_u32(sm + AVL + buf * 8192);

    // ---- S = Qh K^T (2-pass fp16: Kh then Kl) ----
    float s[8][4];
#pragma unroll
    for (int j = 0; j < 8; j++)
#pragma unroll
      for (int r = 0; r < 4; r++) s[j][r] = 0.f;

#pragma unroll
    for (int kt = 0; kt < 4; kt++) {
      const uint32_t xo = ((uint32_t)(kt * 32 + t * 4)) ^ xg;
      const char* qrh = Qh + r0 * 128;
      uint32_t ah0 = ldu(qrh + xo),        ah1 = ldu(qrh + 1024 + xo);
      uint32_t ah2 = ldu(qrh + (xo ^ 16)), ah3 = ldu(qrh + 1024 + (xo ^ 16));
#pragma unroll
      for (int j = 0; j < 8; j++) {
        const char* krh = Kh + (j * 8 + g) * 128;
        const char* krl = Kl + (j * 8 + g) * 128;
        uint32_t bh0 = ldu(krh + xo), bh1 = ldu(krh + (xo ^ 16));
        uint32_t bl0 = ldu(krl + xo), bl1 = ldu(krl + (xo ^ 16));
        mma16(s[j], ah0, ah1, ah2, ah3, bh0, bh1);
        mma16(s[j], ah0, ah1, ah2, ah3, bl0, bl1);
      }
    }

    // scale 1/sqrt(64), causal mask on diagonal block
#pragma unroll
    for (int j = 0; j < 8; j++)
#pragma unroll
      for (int r = 0; r < 4; r++) s[j][r] *= 0.125f;

    if (kj == qi) {
#pragma unroll
      for (int j = 0; j < 8; j++) {
        const int c = j * 8 + 2 * t;
        if (c     > r0)     s[j][0] = -1e30f;
        if (c + 1 > r0)     s[j][1] = -1e30f;
        if (c     > r0 + 8) s[j][2] = -1e30f;
        if (c + 1 > r0 + 8) s[j][3] = -1e30f;
      }
    }

    // ---- online softmax (rows r0, r0+8; 4 quad lanes share a row) ----
    float rm0 = -1e30f, rm1 = -1e30f;
#pragma unroll
    for (int j = 0; j < 8; j++) {
      rm0 = fmaxf(rm0, fmaxf(s[j][0], s[j][1]));
      rm1 = fmaxf(rm1, fmaxf(s[j][2], s[j][3]));
    }
    rm0 = fmaxf(rm0, __shfl_xor_sync(0xffffffffu, rm0, 1));
    rm0 = fmaxf(rm0, __shfl_xor_sync(0xffffffffu, rm0, 2));
    rm1 = fmaxf(rm1, __shfl_xor_sync(0xffffffffu, rm1, 1));
    rm1 = fmaxf(rm1, __shfl_xor_sync(0xffffffffu, rm1, 2));
    const float mn0 = fmaxf(m0, rm0), mn1 = fmaxf(m1, rm1);
    const float al_0 = __expf(m0 - mn0), al_1 = __expf(m1 - mn1);
    float rs0 = 0.f, rs1 = 0.f;
#pragma unroll
    for (int j = 0; j < 8; j++) {
      s[j][0] = __expf(s[j][0] - mn0);
      s[j][1] = __expf(s[j][1] - mn0);
      s[j][2] = __expf(s[j][2] - mn1);
      s[j][3] = __expf(s[j][3] - mn1);
      rs0 += s[j][0] + s[j][1];
      rs1 += s[j][2] + s[j][3];
    }
    rs0 += __shfl_xor_sync(0xffffffffu, rs0, 1);
    rs0 += __shfl_xor_sync(0xffffffffu, rs0, 2);
    rs1 += __shfl_xor_sync(0xffffffffu, rs1, 1);
    rs1 += __shfl_xor_sync(0xffffffffu, rs1, 2);
    l0 = l0 * al_0 + rs0;  m0 = mn0;
    l1 = l1 * al_1 + rs1;  m1 = mn1;
#pragma unroll
    for (int j = 0; j < 8; j++) {
      o[j][0] *= al_0; o[j][1] *= al_0;
      o[j][2] *= al_1; o[j][3] *= al_1;
    }

    // ---- P -> fp16 hi only, in registers (acc layout == A-frag layout) ----
    uint32_t ph01[8], ph23[8];
#pragma unroll
    for (int j = 0; j < 8; j++) {
      ph01[j] = pack_h2(s[j][0], s[j][1]);
      ph23[j] = pack_h2(s[j][2], s[j][3]);
    }

    // ---- O += Ph V (2-pass: Vh then Vl; V^T via ldmatrix.x4.trans) ----
    const int qq = lane >> 3, rr = lane & 7;
#pragma unroll
    for (int kt = 0; kt < 4; kt++) {
      const uint32_t pa0 = ph01[2*kt],   pa1 = ph23[2*kt];
      const uint32_t pa2 = ph01[2*kt+1], pa3 = ph23[2*kt+1];
      const uint32_t vrow = (uint32_t)(kt * 16 + ((qq & 1) << 3) + rr);
#pragma unroll
      for (int jp = 0; jp < 4; jp++) {
        const uint32_t off = sw128(vrow * 128 + (uint32_t)(jp * 32 + ((qq >> 1) << 4)));
        uint32_t vh0, vh1, vh2, vh3, vl0, vl1, vl2, vl3;
        ldsm4t(vh0, vh1, vh2, vh3, vhU + off);
        ldsm4t(vl0, vl1, vl2, vl3, vlU + off);
        mma16(o[2*jp],     pa0, pa1, pa2, pa3, vh0, vh1);
        mma16(o[2*jp],     pa0, pa1, pa2, pa3, vl0, vl1);
        mma16(o[2*jp + 1], pa0, pa1, pa2, pa3, vh2, vh3);
        mma16(o[2*jp + 1], pa0, pa1, pa2, pa3, vl2, vl3);
      }
    }
    __syncthreads();   // tiles consumed before next prefetch overwrites
  }

  // ---- epilogue: O /= l, fp16 hi only ----
  const float i0 = 1.f / l0, i1 = 1.f / l1;
  const size_t ro0 = (rowQ + r0) * CM + h * 64;
  const size_t ro1 = ro0 + 8 * (size_t)CM;
#pragma unroll
  for (int j = 0; j < 8; j++) {
    const int col = j * 8 + 2 * t;
    *(uint32_t*)(oh + ro0 + col) = pack_h2(o[j][0] * i0, o[j][1] * i0);
    *(uint32_t*)(oh + ro1 + col) = pack_h2(o[j][2] * i1, o[j][3] * i1);
  }
}

// ---------------------------------------------------------------------------
extern "C" void kernel_launch(void* const* d_in, const int* in_sizes, int n_in,
                              void* d_out, int out_size) {
  const float* x     = (const float*)d_in[0];   // [4,2048,1024]
  const float* w_qkv = (const float*)d_in[1];   // [3072,1024]
  const float* w_out = (const float*)d_in[2];   // [1024,1024]
  float* out = (float*)d_out;

  __half *xh, *xl, *wqh, *wql, *woh, *wol, *qkvh, *qkvl, *ath;
  cudaGetSymbolAddress((void**)&xh,  g_x_hi);    cudaGetSymbolAddress((void**)&xl,  g_x_lo);
  cudaGetSymbolAddress((void**)&wqh, g_wqkv_hi); cudaGetSymbolAddress((void**)&wql, g_wqkv_lo);
  cudaGetSymbolAddress((void**)&woh, g_wout_hi); cudaGetSymbolAddress((void**)&wol, g_wout_lo);
  cudaGetSymbolAddress((void**)&qkvh, g_qkv_hi); cudaGetSymbolAddress((void**)&qkvl, g_qkv_lo);
  cudaGetSymbolAddress((void**)&ath, g_att_hi);

  cudaFuncSetAttribute(gemm2<0>, cudaFuncAttributeMaxDynamicSharedMemorySize, GSMEM_TOTAL);
  cudaFuncSetAttribute(gemm2<1>, cudaFuncAttributeMaxDynamicSharedMemorySize, GSMEM_TOTAL);
  cudaFuncSetAttribute(attn2,    cudaFuncAttributeMaxDynamicSharedMemorySize, ASMEM_TOTAL);

  // 0) split inputs into fp16 hi/lo (x_lo unused but cheap to produce)
  {
    int n4 = MR * CM / 4;
    split_kernel<<<(n4 + 255) / 256, 256>>>(x, xh, xl, n4);
    n4 = 3 * CM * CM / 4;
    split_kernel<<<(n4 + 255) / 256, 256>>>(w_qkv, wqh, wql, n4);
    n4 = CM * CM / 4;
    split_kernel<<<(n4 + 255) / 256, 256>>>(w_out, woh, wol, n4);
  }

  // 1) QKV projection -> qkv hi/lo fp16 (2-pass: xh*(wh+wl))
  gemm2<1><<<dim3(3*CM/128, MR/128), 256, GSMEM_TOTAL>>>(
      xh, wqh, wql, nullptr, qkvh, qkvl, 3*CM, CM);

  // 2) causal flash attention -> att hi fp16 (2-pass S, 2-pass PV)
  attn2<<<dim3(TT/64, HH, BB), 128, ASMEM_TOTAL>>>(qkvh, qkvl, ath);

  // 3) output projection -> fp32 out (2-pass: ath*(woh+wol))
  gemm2<0><<<dim3(CM/128, MR/128), 256, GSMEM_TOTAL>>>(
      ath, woh, wol, out, nullptr, nullptr, CM, CM);
}

// round 10
// speedup vs baseline: 1.6608x; 1.1200x over previous
#include <cuda_runtime.h>
#include <cuda_fp16.h>
#include <cstdint>

#define CM 1024
#define TT 2048
#define BB 4
#define HH 16
#define MR (BB*TT)   // 8192 rows

// ---------------------------------------------------------------------------
// Scratch (device globals: allocation-free per harness rules). fp16 hi/lo.
// ---------------------------------------------------------------------------
__device__ __half g_x_hi[(size_t)MR * CM];
__device__ __half g_wqkv_hi[3 * CM * CM],        g_wqkv_lo[3 * CM * CM];
__device__ __half g_wout_hi[CM * CM];
__device__ __half g_qkv_hi[(size_t)MR * 3 * CM], g_qkv_lo[(size_t)MR * 3 * CM];
__device__ __half g_att_hi[(size_t)MR * CM];

// ---------------------------------------------------------------------------
// helpers
// ---------------------------------------------------------------------------
__device__ __forceinline__ uint32_t smem_u32(const void* p) {
  uint32_t a;
  asm("{ .reg .u64 t; cvta.to.shared.u64 t, %1; cvt.u32.u64 %0, t; }"
      : "=r"(a) : "l"(p));
  return a;
}
__device__ __forceinline__ void cp16(uint32_t s, const void* g) {
  asm volatile("cp.async.cg.shared.global [%0], [%1], 16;" :: "r"(s), "l"(g));
}
#define CP_COMMIT() asm volatile("cp.async.commit_group;" ::: "memory")
#define CP_WAIT(n)  asm volatile("cp.async.wait_group %0;" :: "n"(n) : "memory")

// D += A*B, m16n8k16 fp16 operands, fp32 accumulate
__device__ __forceinline__ void mma16(float* d, uint32_t a0, uint32_t a1,
                                      uint32_t a2, uint32_t a3,
                                      uint32_t b0, uint32_t b1) {
  asm volatile(
      "mma.sync.aligned.m16n8k16.row.col.f32.f16.f16.f32 "
      "{%0,%1,%2,%3}, {%4,%5,%6,%7}, {%8,%9}, {%0,%1,%2,%3};"
      : "+f"(d[0]), "+f"(d[1]), "+f"(d[2]), "+f"(d[3])
      : "r"(a0), "r"(a1), "r"(a2), "r"(a3), "r"(b0), "r"(b1));
}
__device__ __forceinline__ void ldsm4t(uint32_t& r0, uint32_t& r1,
                                       uint32_t& r2, uint32_t& r3, uint32_t a) {
  asm volatile("ldmatrix.sync.aligned.m8n8.x4.trans.shared.b16 "
               "{%0,%1,%2,%3}, [%4];"
               : "=r"(r0), "=r"(r1), "=r"(r2), "=r"(r3) : "r"(a));
}
__device__ __forceinline__ uint32_t ldu(const void* p) {
  return *(const uint32_t*)p;
}
__device__ __forceinline__ uint32_t sw128(uint32_t o) { return o ^ ((o >> 3) & 0x70); }

// split fp32 -> fp16 hi + fp16 lo
__device__ __forceinline__ void split1(float x, uint16_t& h, uint16_t& l) {
  __half hh = __float2half_rn(x);
  float r = x - __half2float(hh);
  __half hl = __float2half_rn(r);
  h = __half_as_ushort(hh);
  l = __half_as_ushort(hl);
}
__device__ __forceinline__ uint32_t pack_h2(float a, float b) {
  __half2 p = __floats2half2_rn(a, b);
  return *(uint32_t*)&p;
}

// ---------------------------------------------------------------------------
// elementwise splits
// ---------------------------------------------------------------------------
__global__ __launch_bounds__(256) void split_kernel(
    const float* __restrict__ in, __half* __restrict__ hi,
    __half* __restrict__ lo, int n4) {
  int i = blockIdx.x * blockDim.x + threadIdx.x;
  if (i >= n4) return;
  float4 v = ((const float4*)in)[i];
  uint16_t h0, h1, h2, h3, l0, l1, l2, l3;
  split1(v.x, h0, l0); split1(v.y, h1, l1);
  split1(v.z, h2, l2); split1(v.w, h3, l3);
  ((uint2*)hi)[i] = make_uint2(h0 | ((uint32_t)h1 << 16), h2 | ((uint32_t)h3 << 16));
  ((uint2*)lo)[i] = make_uint2(l0 | ((uint32_t)l1 << 16), l2 | ((uint32_t)l3 << 16));
}

__global__ __launch_bounds__(256) void split_hi_kernel(
    const float* __restrict__ in, __half* __restrict__ hi, int n4) {
  int i = blockIdx.x * blockDim.x + threadIdx.x;
  if (i >= n4) return;
  float4 v = ((const float4*)in)[i];
  ((uint2*)hi)[i] = make_uint2(pack_h2(v.x, v.y), pack_h2(v.z, v.w));
}

// ---------------------------------------------------------------------------
// fp16 TN GEMM: C[M,N] ~= Ah*(Bh[+Bl])^T.  NB = # B buffers (1 or 2 passes).
// CTA 128x128, BK=64, 3-stage cp.async, 256 threads (8 warps: 2x4, 64x32 each)
// Register double-buffered fragments (best-measured structure).
// MODE 0: write fp32 C.  MODE 1: write fp16 hi/lo C.
// ---------------------------------------------------------------------------
template<int MODE, int NB>
__global__ __launch_bounds__(256) void gemmN(
    const __half* __restrict__ Ah_,
    const __half* __restrict__ Bh_, const __half* __restrict__ Bl_,
    float* __restrict__ Cf, __half* __restrict__ Chi,
    __half* __restrict__ Clo, int N, int K) {
  constexpr int STAGE = (1 + NB) * 16384;
  extern __shared__ char sm[];
  const int tid = threadIdx.x, w = tid >> 5, lane = tid & 31;
  const int g = lane >> 2, t = lane & 3;
  const int wm = w & 1, wn = w >> 1;
  const int bm = blockIdx.y * 128, bn = blockIdx.x * 128;

  float acc[4][4][4];
#pragma unroll
  for (int mt = 0; mt < 4; mt++)
#pragma unroll
    for (int nt = 0; nt < 4; nt++)
#pragma unroll
      for (int r = 0; r < 4; r++) acc[mt][nt][r] = 0.f;

  // stage: Ah | Bh [| Bl], each 128 rows x 128B (64 fp16), SW128 swizzled
  auto fill = [&](int s, int k0) {
    char* base = sm + s * STAGE;
#pragma unroll
    for (int i = tid; i < (1 + NB) * 1024; i += 256) {
      int buf = i >> 10;            // 0=Ah, 1=Bh, 2=Bl
      int row = (i >> 3) & 127;
      int c = i & 7;
      uint32_t swo = sw128((uint32_t)(row * 128 + c * 16));
      size_t off = (size_t)((buf ? bn : bm) + row) * K + k0 + c * 8;
      const __half* src = (buf == 0) ? Ah_ + off
                        : (buf == 1) ? Bh_ + off : Bl_ + off;
      cp16(smem_u32(base + buf * 16384 + swo), src);
    }
  };

  const int KT = K >> 6;
  fill(0, 0);   CP_COMMIT();
  fill(1, 64);  CP_COMMIT();
  fill(2, 128); CP_COMMIT();

  const uint32_t xg = (uint32_t)g << 4;

  for (int c = 0; c < KT; c++) {
    const int s = c - (c / 3) * 3;
    CP_WAIT(2);
    __syncthreads();
    const char* Ah = sm + s * STAGE;
    const char* Bh = Ah + 16384;
    const char* Bl = Ah + 32768;   // valid only if NB==2

    uint32_t ah[2][4][4], bh[2][4][2], bl[2][4][2];

    auto loadFrags = [&](int kt, int buf) {
      const uint32_t xo = ((uint32_t)(kt * 32 + t * 4)) ^ xg;
#pragma unroll
      for (int mt = 0; mt < 4; mt++) {
        const char* ar = Ah + (wm * 64 + mt * 16 + g) * 128;
        ah[buf][mt][0] = ldu(ar + xo);
        ah[buf][mt][1] = ldu(ar + 1024 + xo);
        ah[buf][mt][2] = ldu(ar + (xo ^ 16));
        ah[buf][mt][3] = ldu(ar + 1024 + (xo ^ 16));
      }
#pragma unroll
      for (int nt = 0; nt < 4; nt++) {
        const char* br = Bh + (wn * 32 + nt * 8 + g) * 128;
        bh[buf][nt][0] = ldu(br + xo);
        bh[buf][nt][1] = ldu(br + (xo ^ 16));
        if (NB == 2) {
          const char* brl = Bl + (wn * 32 + nt * 8 + g) * 128;
          bl[buf][nt][0] = ldu(brl + xo);
          bl[buf][nt][1] = ldu(brl + (xo ^ 16));
        }
      }
    };

    loadFrags(0, 0);
#pragma unroll
    for (int kt = 0; kt < 4; kt++) {
      const int cur = kt & 1;
      if (kt < 3) loadFrags(kt + 1, cur ^ 1);   // prefetch next kt's fragments
#pragma unroll
      for (int nt = 0; nt < 4; nt++) {
#pragma unroll
        for (int mt = 0; mt < 4; mt++) {
          mma16(acc[mt][nt], ah[cur][mt][0], ah[cur][mt][1],
                ah[cur][mt][2], ah[cur][mt][3], bh[cur][nt][0], bh[cur][nt][1]);
          if (NB == 2)
            mma16(acc[mt][nt], ah[cur][mt][0], ah[cur][mt][1],
                  ah[cur][mt][2], ah[cur][mt][3], bl[cur][nt][0], bl[cur][nt][1]);
        }
      }
    }
    __syncthreads();
    if (c + 3 < KT) fill(s, (c + 3) * 64);
    CP_COMMIT();
  }

#pragma unroll
  for (int mt = 0; mt < 4; mt++) {
#pragma unroll
    for (int nt = 0; nt < 4; nt++) {
      const int row = bm + wm * 64 + mt * 16 + g;
      const int col = bn + wn * 32 + nt * 8 + 2 * t;
      if (MODE == 0) {
        *(float2*)(Cf + (size_t)row * N + col) =
            make_float2(acc[mt][nt][0], acc[mt][nt][1]);
        *(float2*)(Cf + (size_t)(row + 8) * N + col) =
            make_float2(acc[mt][nt][2], acc[mt][nt][3]);
      } else {
        uint16_t h0, l0, h1, l1;
        split1(acc[mt][nt][0], h0, l0); split1(acc[mt][nt][1], h1, l1);
        *(uint32_t*)(Chi + (size_t)row * N + col) = h0 | ((uint32_t)h1 << 16);
        *(uint32_t*)(Clo + (size_t)row * N + col) = l0 | ((uint32_t)l1 << 16);
        split1(acc[mt][nt][2], h0, l0); split1(acc[mt][nt][3], h1, l1);
        *(uint32_t*)(Chi + (size_t)(row + 8) * N + col) = h0 | ((uint32_t)h1 << 16);
        *(uint32_t*)(Clo + (size_t)(row + 8) * N + col) = l0 | ((uint32_t)l1 << 16);
      }
    }
  }
}

#define GSMEM_QKV (3 * 49152)   // Ah|Bh|Bl stages
#define GSMEM_PRJ (3 * 32768)   // Ah|Bh stages

// ---------------------------------------------------------------------------
// fp16 causal flash attention:
//   S  = Qh*Kh^T + Qh*Kl^T      (Ql dropped)
//   O += Ph*Vh                  (Pl, Vl dropped)
// Output: hi fp16 only. SMEM: Qh 8K | Kh x2 16K | Kl x2 16K | Vh x2 16K = 56KB
// ---------------------------------------------------------------------------
#define AQH 0
#define AKH 8192
#define AKL 24576
#define AVH 40960
#define ASMEM_TOTAL 57344

__global__ __launch_bounds__(128) void attn2(
    const __half* __restrict__ qh, const __half* __restrict__ ql,
    __half* __restrict__ oh) {
  extern __shared__ char sm[];
  const int qi = blockIdx.x, h = blockIdx.y, b = blockIdx.z;
  const int tid = threadIdx.x, w = tid >> 5, lane = tid & 31;
  const int g = lane >> 2, t = lane & 3;
  const int q0 = qi * 64;
  const int r0 = w * 16 + g;
  const size_t rowQ = (size_t)(b * TT + q0);

  auto fillKV = [&](int kb, int bf) {
    const size_t base = (size_t)(b * TT + kb * 64) * 3 * CM + CM + h * 64;
    char* kh = sm + AKH + bf * 8192;
    char* kl = sm + AKL + bf * 8192;
    char* vh = sm + AVH + bf * 8192;
#pragma unroll
    for (int i = tid; i < 512; i += 128) {
      int row = i >> 3, c = i & 7;
      uint32_t swo = sw128((uint32_t)(row * 128 + c * 16));
      size_t src = base + (size_t)row * 3 * CM + c * 8;
      cp16(smem_u32(kh + swo), qh + src);
      cp16(smem_u32(kl + swo), ql + src);
      cp16(smem_u32(vh + swo), qh + src + CM);
    }
  };

  // prologue: Qh + KV block 0, one group
#pragma unroll
  for (int i = tid; i < 512; i += 128) {
    int row = i >> 3, c = i & 7;
    uint32_t swo = sw128((uint32_t)(row * 128 + c * 16));
    size_t src = (rowQ + row) * 3 * CM + h * 64 + c * 8;
    cp16(smem_u32(sm + AQH + swo), qh + src);
  }
  fillKV(0, 0);
  CP_COMMIT();

  float m0 = -1e30f, m1 = -1e30f, l0 = 0.f, l1 = 0.f;
  float o[8][4];
#pragma unroll
  for (int j = 0; j < 8; j++)
#pragma unroll
    for (int r = 0; r < 4; r++) o[j][r] = 0.f;

  const uint32_t xg = (uint32_t)g << 4;

  for (int kj = 0; kj <= qi; kj++) {
    const int buf = kj & 1;
    if (kj < qi) fillKV(kj + 1, buf ^ 1);
    CP_COMMIT();
    CP_WAIT(1);
    __syncthreads();

    const char* Kh = sm + AKH + buf * 8192;
    const char* Kl = sm + AKL + buf * 8192;
    const char* Qh = sm + AQH;
    const uint32_t vhU = smem_u32(sm + AVH + buf * 8192);

    // ---- S = Qh K^T (2-pass: Kh then Kl) ----
    float s[8][4];
#pragma unroll
    for (int j = 0; j < 8; j++)
#pragma unroll
      for (int r = 0; r < 4; r++) s[j][r] = 0.f;

#pragma unroll
    for (int kt = 0; kt < 4; kt++) {
      const uint32_t xo = ((uint32_t)(kt * 32 + t * 4)) ^ xg;
      const char* qrh = Qh + r0 * 128;
      uint32_t ah0 = ldu(qrh + xo),        ah1 = ldu(qrh + 1024 + xo);
      uint32_t ah2 = ldu(qrh + (xo ^ 16)), ah3 = ldu(qrh + 1024 + (xo ^ 16));
#pragma unroll
      for (int j = 0; j < 8; j++) {
        const char* krh = Kh + (j * 8 + g) * 128;
        const char* krl = Kl + (j * 8 + g) * 128;
        uint32_t bh0 = ldu(krh + xo), bh1 = ldu(krh + (xo ^ 16));
        uint32_t bl0 = ldu(krl + xo), bl1 = ldu(krl + (xo ^ 16));
        mma16(s[j], ah0, ah1, ah2, ah3, bh0, bh1);
        mma16(s[j], ah0, ah1, ah2, ah3, bl0, bl1);
      }
    }

    // scale 1/sqrt(64), causal mask on diagonal block
#pragma unroll
    for (int j = 0; j < 8; j++)
#pragma unroll
      for (int r = 0; r < 4; r++) s[j][r] *= 0.125f;

    if (kj == qi) {
#pragma unroll
      for (int j = 0; j < 8; j++) {
        const int c = j * 8 + 2 * t;
        if (c     > r0)     s[j][0] = -1e30f;
        if (c + 1 > r0)     s[j][1] = -1e30f;
        if (c     > r0 + 8) s[j][2] = -1e30f;
        if (c + 1 > r0 + 8) s[j][3] = -1e30f;
      }
    }

    // ---- online softmax (rows r0, r0+8; 4 quad lanes share a row) ----
    float rm0 = -1e30f, rm1 = -1e30f;
#pragma unroll
    for (int j = 0; j < 8; j++) {
      rm0 = fmaxf(rm0, fmaxf(s[j][0], s[j][1]));
      rm1 = fmaxf(rm1, fmaxf(s[j][2], s[j][3]));
    }
    rm0 = fmaxf(rm0, __shfl_xor_sync(0xffffffffu, rm0, 1));
    rm0 = fmaxf(rm0, __shfl_xor_sync(0xffffffffu, rm0, 2));
    rm1 = fmaxf(rm1, __shfl_xor_sync(0xffffffffu, rm1, 1));
    rm1 = fmaxf(rm1, __shfl_xor_sync(0xffffffffu, rm1, 2));
    const float mn0 = fmaxf(m0, rm0), mn1 = fmaxf(m1, rm1);
    const float al_0 = __expf(m0 - mn0), al_1 = __expf(m1 - mn1);
    float rs0 = 0.f, rs1 = 0.f;
#pragma unroll
    for (int j = 0; j < 8; j++) {
      s[j][0] = __expf(s[j][0] - mn0);
      s[j][1] = __expf(s[j][1] - mn0);
      s[j][2] = __expf(s[j][2] - mn1);
      s[j][3] = __expf(s[j][3] - mn1);
      rs0 += s[j][0] + s[j][1];
      rs1 += s[j][2] + s[j][3];
    }
    rs0 += __shfl_xor_sync(0xffffffffu, rs0, 1);
    rs0 += __shfl_xor_sync(0xffffffffu, rs0, 2);
    rs1 += __shfl_xor_sync(0xffffffffu, rs1, 1);
    rs1 += __shfl_xor_sync(0xffffffffu, rs1, 2);
    l0 = l0 * al_0 + rs0;  m0 = mn0;
    l1 = l1 * al_1 + rs1;  m1 = mn1;
#pragma unroll
    for (int j = 0; j < 8; j++) {
      o[j][0] *= al_0; o[j][1] *= al_0;
      o[j][2] *= al_1; o[j][3] *= al_1;
    }

    // ---- P -> fp16 hi only, in registers (acc layout == A-frag layout) ----
    uint32_t ph01[8], ph23[8];
#pragma unroll
    for (int j = 0; j < 8; j++) {
      ph01[j] = pack_h2(s[j][0], s[j][1]);
      ph23[j] = pack_h2(s[j][2], s[j][3]);
    }

    // ---- O += Ph Vh (1-pass; V^T via ldmatrix.x4.trans) ----
    const int qq = lane >> 3, rr = lane & 7;
#pragma unroll
    for (int kt = 0; kt < 4; kt++) {
      const uint32_t pa0 = ph01[2*kt],   pa1 = ph23[2*kt];
      const uint32_t pa2 = ph01[2*kt+1], pa3 = ph23[2*kt+1];
      const uint32_t vrow = (uint32_t)(kt * 16 + ((qq & 1) << 3) + rr);
#pragma unroll
      for (int jp = 0; jp < 4; jp++) {
        const uint32_t off = sw128(vrow * 128 + (uint32_t)(jp * 32 + ((qq >> 1) << 4)));
        uint32_t vh0, vh1, vh2, vh3;
        ldsm4t(vh0, vh1, vh2, vh3, vhU + off);
        mma16(o[2*jp],     pa0, pa1, pa2, pa3, vh0, vh1);
        mma16(o[2*jp + 1], pa0, pa1, pa2, pa3, vh2, vh3);
      }
    }
    __syncthreads();   // tiles consumed before next prefetch overwrites
  }

  // ---- epilogue: O /= l, fp16 hi only ----
  const float i0 = 1.f / l0, i1 = 1.f / l1;
  const size_t ro0 = (rowQ + r0) * CM + h * 64;
  const size_t ro1 = ro0 + 8 * (size_t)CM;
#pragma unroll
  for (int j = 0; j < 8; j++) {
    const int col = j * 8 + 2 * t;
    *(uint32_t*)(oh + ro0 + col) = pack_h2(o[j][0] * i0, o[j][1] * i0);
    *(uint32_t*)(oh + ro1 + col) = pack_h2(o[j][2] * i1, o[j][3] * i1);
  }
}

// ---------------------------------------------------------------------------
extern "C" void kernel_launch(void* const* d_in, const int* in_sizes, int n_in,
                              void* d_out, int out_size) {
  const float* x     = (const float*)d_in[0];   // [4,2048,1024]
  const float* w_qkv = (const float*)d_in[1];   // [3072,1024]
  const float* w_out = (const float*)d_in[2];   // [1024,1024]
  float* out = (float*)d_out;

  __half *xh, *wqh, *wql, *woh, *qkvh, *qkvl, *ath;
  cudaGetSymbolAddress((void**)&xh,  g_x_hi);
  cudaGetSymbolAddress((void**)&wqh, g_wqkv_hi);
  cudaGetSymbolAddress((void**)&wql, g_wqkv_lo);
  cudaGetSymbolAddress((void**)&woh, g_wout_hi);
  cudaGetSymbolAddress((void**)&qkvh, g_qkv_hi);
  cudaGetSymbolAddress((void**)&qkvl, g_qkv_lo);
  cudaGetSymbolAddress((void**)&ath, g_att_hi);

  cudaFuncSetAttribute(gemmN<1,2>, cudaFuncAttributeMaxDynamicSharedMemorySize, GSMEM_QKV);
  cudaFuncSetAttribute(gemmN<0,1>, cudaFuncAttributeMaxDynamicSharedMemorySize, GSMEM_PRJ);
  cudaFuncSetAttribute(attn2,      cudaFuncAttributeMaxDynamicSharedMemorySize, ASMEM_TOTAL);

  // 0) split inputs (x, w_out hi-only; w_qkv hi+lo)
  {
    int n4 = MR * CM / 4;
    split_hi_kernel<<<(n4 + 255) / 256, 256>>>(x, xh, n4);
    n4 = 3 * CM * CM / 4;
    split_kernel<<<(n4 + 255) / 256, 256>>>(w_qkv, wqh, wql, n4);
    n4 = CM * CM / 4;
    split_hi_kernel<<<(n4 + 255) / 256, 256>>>(w_out, woh, n4);
  }

  // 1) QKV projection -> qkv hi/lo fp16 (2-pass: xh*(wh+wl))
  gemmN<1,2><<<dim3(3*CM/128, MR/128), 256, GSMEM_QKV>>>(
      xh, wqh, wql, nullptr, qkvh, qkvl, 3*CM, CM);

  // 2) causal flash attention -> att hi fp16 (2-pass S, 1-pass PV)
  attn2<<<dim3(TT/64, HH, BB), 128, ASMEM_TOTAL>>>(qkvh, qkvl, ath);

  // 3) output projection -> fp32 out (1-pass: ath*woh)
  gemmN<0,1><<<dim3(CM/128, MR/128), 256, GSMEM_PRJ>>>(
      ath, woh, nullptr, out, nullptr, nullptr, CM, CM);
}

// round 11
// speedup vs baseline: 2.3609x; 1.4215x over previous
#include <cuda_runtime.h>
#include <cuda_fp16.h>
#include <cstdint>

#define CM 1024
#define TT 2048
#define BB 4
#define HH 16
#define MR (BB*TT)   // 8192 rows

// ---------------------------------------------------------------------------
// Scratch (device globals: allocation-free per harness rules). fp16 hi.
// ---------------------------------------------------------------------------
__device__ __half g_x_hi[(size_t)MR * CM];
__device__ __half g_wqkv_hi[3 * CM * CM];
__device__ __half g_wout_hi[CM * CM];
__device__ __half g_qkv_hi[(size_t)MR * 3 * CM];
__device__ __half g_att_hi[(size_t)MR * CM];

// ---------------------------------------------------------------------------
// helpers
// ---------------------------------------------------------------------------
__device__ __forceinline__ uint32_t smem_u32(const void* p) {
  uint32_t a;
  asm("{ .reg .u64 t; cvta.to.shared.u64 t, %1; cvt.u32.u64 %0, t; }"
      : "=r"(a) : "l"(p));
  return a;
}
__device__ __forceinline__ void cp16(uint32_t s, const void* g) {
  asm volatile("cp.async.cg.shared.global [%0], [%1], 16;" :: "r"(s), "l"(g));
}
#define CP_COMMIT() asm volatile("cp.async.commit_group;" ::: "memory")
#define CP_WAIT(n)  asm volatile("cp.async.wait_group %0;" :: "n"(n) : "memory")

// D += A*B, m16n8k16 fp16 operands, fp32 accumulate
__device__ __forceinline__ void mma16(float* d, uint32_t a0, uint32_t a1,
                                      uint32_t a2, uint32_t a3,
                                      uint32_t b0, uint32_t b1) {
  asm volatile(
      "mma.sync.aligned.m16n8k16.row.col.f32.f16.f16.f32 "
      "{%0,%1,%2,%3}, {%4,%5,%6,%7}, {%8,%9}, {%0,%1,%2,%3};"
      : "+f"(d[0]), "+f"(d[1]), "+f"(d[2]), "+f"(d[3])
      : "r"(a0), "r"(a1), "r"(a2), "r"(a3), "r"(b0), "r"(b1));
}
__device__ __forceinline__ void ldsm4t(uint32_t& r0, uint32_t& r1,
                                       uint32_t& r2, uint32_t& r3, uint32_t a) {
  asm volatile("ldmatrix.sync.aligned.m8n8.x4.trans.shared.b16 "
               "{%0,%1,%2,%3}, [%4];"
               : "=r"(r0), "=r"(r1), "=r"(r2), "=r"(r3) : "r"(a));
}
__device__ __forceinline__ uint32_t ldu(const void* p) {
  return *(const uint32_t*)p;
}
__device__ __forceinline__ uint32_t sw128(uint32_t o) { return o ^ ((o >> 3) & 0x70); }

__device__ __forceinline__ uint32_t pack_h2(float a, float b) {
  __half2 p = __floats2half2_rn(a, b);
  return *(uint32_t*)&p;
}

// ---------------------------------------------------------------------------
// elementwise cast: fp32 -> fp16
// ---------------------------------------------------------------------------
__global__ __launch_bounds__(256) void split_hi_kernel(
    const float* __restrict__ in, __half* __restrict__ hi, int n4) {
  int i = blockIdx.x * blockDim.x + threadIdx.x;
  if (i >= n4) return;
  float4 v = ((const float4*)in)[i];
  ((uint2*)hi)[i] = make_uint2(pack_h2(v.x, v.y), pack_h2(v.z, v.w));
}

// ---------------------------------------------------------------------------
// fp16 TN GEMM: C[M,N] = Ah[M,K] * Bh[N,K]^T, fp32 accumulate.
// CTA 128x128, BK=64, 3-stage cp.async, 256 threads (8 warps: 2x4, 64x32 each)
// Register double-buffered fragments (best-measured structure).
// MODE 0: write fp32 C.  MODE 1: write fp16 C.
// ---------------------------------------------------------------------------
#define GSTAGE 32768                    // Ah 16K | Bh 16K
#define GSMEM_TOTAL (3 * GSTAGE)        // 96 KB

template<int MODE>
__global__ __launch_bounds__(256) void gemmH(
    const __half* __restrict__ Ah_, const __half* __restrict__ Bh_,
    float* __restrict__ Cf, __half* __restrict__ Ch, int N, int K) {
  extern __shared__ char sm[];
  const int tid = threadIdx.x, w = tid >> 5, lane = tid & 31;
  const int g = lane >> 2, t = lane & 3;
  const int wm = w & 1, wn = w >> 1;
  const int bm = blockIdx.y * 128, bn = blockIdx.x * 128;

  float acc[4][4][4];
#pragma unroll
  for (int mt = 0; mt < 4; mt++)
#pragma unroll
    for (int nt = 0; nt < 4; nt++)
#pragma unroll
      for (int r = 0; r < 4; r++) acc[mt][nt][r] = 0.f;

  // stage: Ah | Bh, each 128 rows x 128B (64 fp16), SW128 swizzled
  auto fill = [&](int s, int k0) {
    char* base = sm + s * GSTAGE;
#pragma unroll
    for (int i = tid; i < 2048; i += 256) {
      int buf = i >> 10;            // 0=Ah, 1=Bh
      int row = (i >> 3) & 127;
      int c = i & 7;
      uint32_t swo = sw128((uint32_t)(row * 128 + c * 16));
      size_t off = (size_t)((buf ? bn : bm) + row) * K + k0 + c * 8;
      cp16(smem_u32(base + buf * 16384 + swo), (buf ? Bh_ : Ah_) + off);
    }
  };

  const int KT = K >> 6;
  fill(0, 0);   CP_COMMIT();
  fill(1, 64);  CP_COMMIT();
  fill(2, 128); CP_COMMIT();

  const uint32_t xg = (uint32_t)g << 4;

  for (int c = 0; c < KT; c++) {
    const int s = c - (c / 3) * 3;
    CP_WAIT(2);
    __syncthreads();
    const char* Ah = sm + s * GSTAGE;
    const char* Bh = Ah + 16384;

    uint32_t ah[2][4][4], bh[2][4][2];

    auto loadFrags = [&](int kt, int buf) {
      const uint32_t xo = ((uint32_t)(kt * 32 + t * 4)) ^ xg;
#pragma unroll
      for (int mt = 0; mt < 4; mt++) {
        const char* ar = Ah + (wm * 64 + mt * 16 + g) * 128;
        ah[buf][mt][0] = ldu(ar + xo);
        ah[buf][mt][1] = ldu(ar + 1024 + xo);
        ah[buf][mt][2] = ldu(ar + (xo ^ 16));
        ah[buf][mt][3] = ldu(ar + 1024 + (xo ^ 16));
      }
#pragma unroll
      for (int nt = 0; nt < 4; nt++) {
        const char* br = Bh + (wn * 32 + nt * 8 + g) * 128;
        bh[buf][nt][0] = ldu(br + xo);
        bh[buf][nt][1] = ldu(br + (xo ^ 16));
      }
    };

    loadFrags(0, 0);
#pragma unroll
    for (int kt = 0; kt < 4; kt++) {
      const int cur = kt & 1;
      if (kt < 3) loadFrags(kt + 1, cur ^ 1);   // prefetch next kt's fragments
#pragma unroll
      for (int nt = 0; nt < 4; nt++)
#pragma unroll
        for (int mt = 0; mt < 4; mt++)
          mma16(acc[mt][nt], ah[cur][mt][0], ah[cur][mt][1],
                ah[cur][mt][2], ah[cur][mt][3], bh[cur][nt][0], bh[cur][nt][1]);
    }
    __syncthreads();
    if (c + 3 < KT) fill(s, (c + 3) * 64);
    CP_COMMIT();
  }

#pragma unroll
  for (int mt = 0; mt < 4; mt++) {
#pragma unroll
    for (int nt = 0; nt < 4; nt++) {
      const int row = bm + wm * 64 + mt * 16 + g;
      const int col = bn + wn * 32 + nt * 8 + 2 * t;
      if (MODE == 0) {
        *(float2*)(Cf + (size_t)row * N + col) =
            make_float2(acc[mt][nt][0], acc[mt][nt][1]);
        *(float2*)(Cf + (size_t)(row + 8) * N + col) =
            make_float2(acc[mt][nt][2], acc[mt][nt][3]);
      } else {
        *(uint32_t*)(Ch + (size_t)row * N + col) =
            pack_h2(acc[mt][nt][0], acc[mt][nt][1]);
        *(uint32_t*)(Ch + (size_t)(row + 8) * N + col) =
            pack_h2(acc[mt][nt][2], acc[mt][nt][3]);
      }
    }
  }
}

// ---------------------------------------------------------------------------
// fp16 causal flash attention, 1-pass per matmul:
//   S = Qh*Kh^T ; O += Ph*Vh
// Output: fp16. SMEM: Qh 8K | Kh x2 16K | Vh x2 16K = 40KB
// ---------------------------------------------------------------------------
#define AQH 0
#define AKH 8192
#define AVH 24576
#define ASMEM_TOTAL 40960

__global__ __launch_bounds__(128) void attn1(
    const __half* __restrict__ qh, __half* __restrict__ oh) {
  extern __shared__ char sm[];
  const int qi = blockIdx.x, h = blockIdx.y, b = blockIdx.z;
  const int tid = threadIdx.x, w = tid >> 5, lane = tid & 31;
  const int g = lane >> 2, t = lane & 3;
  const int q0 = qi * 64;
  const int r0 = w * 16 + g;
  const size_t rowQ = (size_t)(b * TT + q0);

  auto fillKV = [&](int kb, int bf) {
    const size_t base = (size_t)(b * TT + kb * 64) * 3 * CM + CM + h * 64;
    char* kh = sm + AKH + bf * 8192;
    char* vh = sm + AVH + bf * 8192;
#pragma unroll
    for (int i = tid; i < 512; i += 128) {
      int row = i >> 3, c = i & 7;
      uint32_t swo = sw128((uint32_t)(row * 128 + c * 16));
      size_t src = base + (size_t)row * 3 * CM + c * 8;
      cp16(smem_u32(kh + swo), qh + src);
      cp16(smem_u32(vh + swo), qh + src + CM);
    }
  };

  // prologue: Qh + KV block 0, one group
#pragma unroll
  for (int i = tid; i < 512; i += 128) {
    int row = i >> 3, c = i & 7;
    uint32_t swo = sw128((uint32_t)(row * 128 + c * 16));
    size_t src = (rowQ + row) * 3 * CM + h * 64 + c * 8;
    cp16(smem_u32(sm + AQH + swo), qh + src);
  }
  fillKV(0, 0);
  CP_COMMIT();

  float m0 = -1e30f, m1 = -1e30f, l0 = 0.f, l1 = 0.f;
  float o[8][4];
#pragma unroll
  for (int j = 0; j < 8; j++)
#pragma unroll
    for (int r = 0; r < 4; r++) o[j][r] = 0.f;

  const uint32_t xg = (uint32_t)g << 4;

  for (int kj = 0; kj <= qi; kj++) {
    const int buf = kj & 1;
    if (kj < qi) fillKV(kj + 1, buf ^ 1);
    CP_COMMIT();
    CP_WAIT(1);
    __syncthreads();

    const char* Kh = sm + AKH + buf * 8192;
    const char* Qh = sm + AQH;
    const uint32_t vhU = smem_u32(sm + AVH + buf * 8192);

    // ---- S = Qh Kh^T (1-pass) ----
    float s[8][4];
#pragma unroll
    for (int j = 0; j < 8; j++)
#pragma unroll
      for (int r = 0; r < 4; r++) s[j][r] = 0.f;

#pragma unroll
    for (int kt = 0; kt < 4; kt++) {
      const uint32_t xo = ((uint32_t)(kt * 32 + t * 4)) ^ xg;
      const char* qrh = Qh + r0 * 128;
      uint32_t ah0 = ldu(qrh + xo),        ah1 = ldu(qrh + 1024 + xo);
      uint32_t ah2 = ldu(qrh + (xo ^ 16)), ah3 = ldu(qrh + 1024 + (xo ^ 16));
#pragma unroll
      for (int j = 0; j < 8; j++) {
        const char* krh = Kh + (j * 8 + g) * 128;
        uint32_t bh0 = ldu(krh + xo), bh1 = ldu(krh + (xo ^ 16));
        mma16(s[j], ah0, ah1, ah2, ah3, bh0, bh1);
      }
    }

    // scale 1/sqrt(64), causal mask on diagonal block
#pragma unroll
    for (int j = 0; j < 8; j++)
#pragma unroll
      for (int r = 0; r < 4; r++) s[j][r] *= 0.125f;

    if (kj == qi) {
#pragma unroll
      for (int j = 0; j < 8; j++) {
        const int c = j * 8 + 2 * t;
        if (c     > r0)     s[j][0] = -1e30f;
        if (c + 1 > r0)     s[j][1] = -1e30f;
        if (c     > r0 + 8) s[j][2] = -1e30f;
        if (c + 1 > r0 + 8) s[j][3] = -1e30f;
      }
    }

    // ---- online softmax (rows r0, r0+8; 4 quad lanes share a row) ----
    float rm0 = -1e30f, rm1 = -1e30f;
#pragma unroll
    for (int j = 0; j < 8; j++) {
      rm0 = fmaxf(rm0, fmaxf(s[j][0], s[j][1]));
      rm1 = fmaxf(rm1, fmaxf(s[j][2], s[j][3]));
    }
    rm0 = fmaxf(rm0, __shfl_xor_sync(0xffffffffu, rm0, 1));
    rm0 = fmaxf(rm0, __shfl_xor_sync(0xffffffffu, rm0, 2));
    rm1 = fmaxf(rm1, __shfl_xor_sync(0xffffffffu, rm1, 1));
    rm1 = fmaxf(rm1, __shfl_xor_sync(0xffffffffu, rm1, 2));
    const float mn0 = fmaxf(m0, rm0), mn1 = fmaxf(m1, rm1);
    const float al_0 = __expf(m0 - mn0), al_1 = __expf(m1 - mn1);
    float rs0 = 0.f, rs1 = 0.f;
#pragma unroll
    for (int j = 0; j < 8; j++) {
      s[j][0] = __expf(s[j][0] - mn0);
      s[j][1] = __expf(s[j][1] - mn0);
      s[j][2] = __expf(s[j][2] - mn1);
      s[j][3] = __expf(s[j][3] - mn1);
      rs0 += s[j][0] + s[j][1];
      rs1 += s[j][2] + s[j][3];
    }
    rs0 += __shfl_xor_sync(0xffffffffu, rs0, 1);
    rs0 += __shfl_xor_sync(0xffffffffu, rs0, 2);
    rs1 += __shfl_xor_sync(0xffffffffu, rs1, 1);
    rs1 += __shfl_xor_sync(0xffffffffu, rs1, 2);
    l0 = l0 * al_0 + rs0;  m0 = mn0;
    l1 = l1 * al_1 + rs1;  m1 = mn1;
#pragma unroll
    for (int j = 0; j < 8; j++) {
      o[j][0] *= al_0; o[j][1] *= al_0;
      o[j][2] *= al_1; o[j][3] *= al_1;
    }

    // ---- P -> fp16, in registers (acc layout == A-frag layout) ----
    uint32_t ph01[8], ph23[8];
#pragma unroll
    for (int j = 0; j < 8; j++) {
      ph01[j] = pack_h2(s[j][0], s[j][1]);
      ph23[j] = pack_h2(s[j][2], s[j][3]);
    }

    // ---- O += Ph Vh (1-pass; V^T via ldmatrix.x4.trans) ----
    const int qq = lane >> 3, rr = lane & 7;
#pragma unroll
    for (int kt = 0; kt < 4; kt++) {
      const uint32_t pa0 = ph01[2*kt],   pa1 = ph23[2*kt];
      const uint32_t pa2 = ph01[2*kt+1], pa3 = ph23[2*kt+1];
      const uint32_t vrow = (uint32_t)(kt * 16 + ((qq & 1) << 3) + rr);
#pragma unroll
      for (int jp = 0; jp < 4; jp++) {
        const uint32_t off = sw128(vrow * 128 + (uint32_t)(jp * 32 + ((qq >> 1) << 4)));
        uint32_t vh0, vh1, vh2, vh3;
        ldsm4t(vh0, vh1, vh2, vh3, vhU + off);
        mma16(o[2*jp],     pa0, pa1, pa2, pa3, vh0, vh1);
        mma16(o[2*jp + 1], pa0, pa1, pa2, pa3, vh2, vh3);
      }
    }
    __syncthreads();   // tiles consumed before next prefetch overwrites
  }

  // ---- epilogue: O /= l, fp16 ----
  const float i0 = 1.f / l0, i1 = 1.f / l1;
  const size_t ro0 = (rowQ + r0) * CM + h * 64;
  const size_t ro1 = ro0 + 8 * (size_t)CM;
#pragma unroll
  for (int j = 0; j < 8; j++) {
    const int col = j * 8 + 2 * t;
    *(uint32_t*)(oh + ro0 + col) = pack_h2(o[j][0] * i0, o[j][1] * i0);
    *(uint32_t*)(oh + ro1 + col) = pack_h2(o[j][2] * i1, o[j][3] * i1);
  }
}

// ---------------------------------------------------------------------------
extern "C" void kernel_launch(void* const* d_in, const int* in_sizes, int n_in,
                              void* d_out, int out_size) {
  const float* x     = (const float*)d_in[0];   // [4,2048,1024]
  const float* w_qkv = (const float*)d_in[1];   // [3072,1024]
  const float* w_out = (const float*)d_in[2];   // [1024,1024]
  float* out = (float*)d_out;

  __half *xh, *wqh, *woh, *qkvh, *ath;
  cudaGetSymbolAddress((void**)&xh,  g_x_hi);
  cudaGetSymbolAddress((void**)&wqh, g_wqkv_hi);
  cudaGetSymbolAddress((void**)&woh, g_wout_hi);
  cudaGetSymbolAddress((void**)&qkvh, g_qkv_hi);
  cudaGetSymbolAddress((void**)&ath, g_att_hi);

  cudaFuncSetAttribute(gemmH<1>, cudaFuncAttributeMaxDynamicSharedMemorySize, GSMEM_TOTAL);
  cudaFuncSetAttribute(gemmH<0>, cudaFuncAttributeMaxDynamicSharedMemorySize, GSMEM_TOTAL);
  cudaFuncSetAttribute(attn1,    cudaFuncAttributeMaxDynamicSharedMemorySize, ASMEM_TOTAL);

  // 0) cast inputs to fp16
  {
    int n4 = MR * CM / 4;
    split_hi_kernel<<<(n4 + 255) / 256, 256>>>(x, xh, n4);
    n4 = 3 * CM * CM / 4;
    split_hi_kernel<<<(n4 + 255) / 256, 256>>>(w_qkv, wqh, n4);
    n4 = CM * CM / 4;
    split_hi_kernel<<<(n4 + 255) / 256, 256>>>(w_out, woh, n4);
  }

  // 1) QKV projection -> qkv fp16 (1-pass)
  gemmH<1><<<dim3(3*CM/128, MR/128), 256, GSMEM_TOTAL>>>(
      xh, wqh, nullptr, qkvh, 3*CM, CM);

  // 2) causal flash attention -> att fp16 (1-pass S, 1-pass PV)
  attn1<<<dim3(TT/64, HH, BB), 128, ASMEM_TOTAL>>>(qkvh, ath);

  // 3) output projection -> fp32 out (1-pass)
  gemmH<0><<<dim3(CM/128, MR/128), 256, GSMEM_TOTAL>>>(
      ath, woh, out, nullptr, CM, CM);
}

// round 12
// speedup vs baseline: 2.4181x; 1.0242x over previous
#include <cuda_runtime.h>
#include <cuda_fp16.h>
#include <cstdint>

#define CM 1024
#define TT 2048
#define BB 4
#define HH 16
#define MR (BB*TT)   // 8192 rows

// ---------------------------------------------------------------------------
// Scratch (device globals: allocation-free per harness rules). fp16.
// ---------------------------------------------------------------------------
__device__ __half g_x_hi[(size_t)MR * CM];
__device__ __half g_wqkv_hi[3 * CM * CM];
__device__ __half g_wout_hi[CM * CM];
__device__ __half g_qkv_hi[(size_t)MR * 3 * CM];
__device__ __half g_att_hi[(size_t)MR * CM];

// ---------------------------------------------------------------------------
// helpers
// ---------------------------------------------------------------------------
__device__ __forceinline__ uint32_t smem_u32(const void* p) {
  uint32_t a;
  asm("{ .reg .u64 t; cvta.to.shared.u64 t, %1; cvt.u32.u64 %0, t; }"
      : "=r"(a) : "l"(p));
  return a;
}
__device__ __forceinline__ void cp16(uint32_t s, const void* g) {
  asm volatile("cp.async.cg.shared.global [%0], [%1], 16;" :: "r"(s), "l"(g));
}
#define CP_COMMIT() asm volatile("cp.async.commit_group;" ::: "memory")
#define CP_WAIT(n)  asm volatile("cp.async.wait_group %0;" :: "n"(n) : "memory")

// D += A*B, m16n8k16 fp16 operands, fp32 accumulate
__device__ __forceinline__ void mma16(float* d, uint32_t a0, uint32_t a1,
                                      uint32_t a2, uint32_t a3,
                                      uint32_t b0, uint32_t b1) {
  asm volatile(
      "mma.sync.aligned.m16n8k16.row.col.f32.f16.f16.f32 "
      "{%0,%1,%2,%3}, {%4,%5,%6,%7}, {%8,%9}, {%0,%1,%2,%3};"
      : "+f"(d[0]), "+f"(d[1]), "+f"(d[2]), "+f"(d[3])
      : "r"(a0), "r"(a1), "r"(a2), "r"(a3), "r"(b0), "r"(b1));
}
__device__ __forceinline__ void ldsm4t(uint32_t& r0, uint32_t& r1,
                                       uint32_t& r2, uint32_t& r3, uint32_t a) {
  asm volatile("ldmatrix.sync.aligned.m8n8.x4.trans.shared.b16 "
               "{%0,%1,%2,%3}, [%4];"
               : "=r"(r0), "=r"(r1), "=r"(r2), "=r"(r3) : "r"(a));
}
__device__ __forceinline__ uint32_t ldu(const void* p) {
  return *(const uint32_t*)p;
}
__device__ __forceinline__ uint32_t sw128(uint32_t o) { return o ^ ((o >> 3) & 0x70); }

__device__ __forceinline__ uint32_t pack_h2(float a, float b) {
  __half2 p = __floats2half2_rn(a, b);
  return *(uint32_t*)&p;
}

// ---------------------------------------------------------------------------
// single fused cast kernel: all three fp32 inputs -> fp16
// ---------------------------------------------------------------------------
#define NX (MR * CM / 4)
#define NW (3 * CM * CM / 4)
#define NO (CM * CM / 4)

__global__ __launch_bounds__(256) void cast_all(
    const float* __restrict__ x, const float* __restrict__ wq,
    const float* __restrict__ wo,
    __half* __restrict__ xh, __half* __restrict__ wqh,
    __half* __restrict__ woh) {
  int i = blockIdx.x * blockDim.x + threadIdx.x;
  const float* src;
  __half* dst;
  int j;
  if (i < NX)            { src = x;  dst = xh;  j = i; }
  else if (i < NX + NW)  { src = wq; dst = wqh; j = i - NX; }
  else if (i < NX + NW + NO) { src = wo; dst = woh; j = i - NX - NW; }
  else return;
  float4 v = ((const float4*)src)[j];
  ((uint2*)dst)[j] = make_uint2(pack_h2(v.x, v.y), pack_h2(v.z, v.w));
}

// ---------------------------------------------------------------------------
// fp16 TN GEMM: C[M,N] = Ah[M,K] * Bh[N,K]^T, fp32 accumulate.
// CTA 128x128, BK=64, 3-stage cp.async, 256 threads (8 warps: 2x4, 64x32 each)
// Register double-buffered fragments (best-measured structure, unchanged).
// MODE 0: write fp32 C.  MODE 1: write fp16 C.
// ---------------------------------------------------------------------------
#define GSTAGE 32768                    // Ah 16K | Bh 16K
#define GSMEM_TOTAL (3 * GSTAGE)        // 96 KB

template<int MODE>
__global__ __launch_bounds__(256) void gemmH(
    const __half* __restrict__ Ah_, const __half* __restrict__ Bh_,
    float* __restrict__ Cf, __half* __restrict__ Ch, int N, int K) {
  extern __shared__ char sm[];
  const int tid = threadIdx.x, w = tid >> 5, lane = tid & 31;
  const int g = lane >> 2, t = lane & 3;
  const int wm = w & 1, wn = w >> 1;
  const int bm = blockIdx.y * 128, bn = blockIdx.x * 128;

  float acc[4][4][4];
#pragma unroll
  for (int mt = 0; mt < 4; mt++)
#pragma unroll
    for (int nt = 0; nt < 4; nt++)
#pragma unroll
      for (int r = 0; r < 4; r++) acc[mt][nt][r] = 0.f;

  auto fill = [&](int s, int k0) {
    char* base = sm + s * GSTAGE;
#pragma unroll
    for (int i = tid; i < 2048; i += 256) {
      int buf = i >> 10;            // 0=Ah, 1=Bh
      int row = (i >> 3) & 127;
      int c = i & 7;
      uint32_t swo = sw128((uint32_t)(row * 128 + c * 16));
      size_t off = (size_t)((buf ? bn : bm) + row) * K + k0 + c * 8;
      cp16(smem_u32(base + buf * 16384 + swo), (buf ? Bh_ : Ah_) + off);
    }
  };

  const int KT = K >> 6;
  fill(0, 0);   CP_COMMIT();
  fill(1, 64);  CP_COMMIT();
  fill(2, 128); CP_COMMIT();

  const uint32_t xg = (uint32_t)g << 4;

  for (int c = 0; c < KT; c++) {
    const int s = c - (c / 3) * 3;
    CP_WAIT(2);
    __syncthreads();
    const char* Ah = sm + s * GSTAGE;
    const char* Bh = Ah + 16384;

    uint32_t ah[2][4][4], bh[2][4][2];

    auto loadFrags = [&](int kt, int buf) {
      const uint32_t xo = ((uint32_t)(kt * 32 + t * 4)) ^ xg;
#pragma unroll
      for (int mt = 0; mt < 4; mt++) {
        const char* ar = Ah + (wm * 64 + mt * 16 + g) * 128;
        ah[buf][mt][0] = ldu(ar + xo);
        ah[buf][mt][1] = ldu(ar + 1024 + xo);
        ah[buf][mt][2] = ldu(ar + (xo ^ 16));
        ah[buf][mt][3] = ldu(ar + 1024 + (xo ^ 16));
      }
#pragma unroll
      for (int nt = 0; nt < 4; nt++) {
        const char* br = Bh + (wn * 32 + nt * 8 + g) * 128;
        bh[buf][nt][0] = ldu(br + xo);
        bh[buf][nt][1] = ldu(br + (xo ^ 16));
      }
    };

    loadFrags(0, 0);
#pragma unroll
    for (int kt = 0; kt < 4; kt++) {
      const int cur = kt & 1;
      if (kt < 3) loadFrags(kt + 1, cur ^ 1);
#pragma unroll
      for (int nt = 0; nt < 4; nt++)
#pragma unroll
        for (int mt = 0; mt < 4; mt++)
          mma16(acc[mt][nt], ah[cur][mt][0], ah[cur][mt][1],
                ah[cur][mt][2], ah[cur][mt][3], bh[cur][nt][0], bh[cur][nt][1]);
    }
    __syncthreads();
    if (c + 3 < KT) fill(s, (c + 3) * 64);
    CP_COMMIT();
  }

#pragma unroll
  for (int mt = 0; mt < 4; mt++) {
#pragma unroll
    for (int nt = 0; nt < 4; nt++) {
      const int row = bm + wm * 64 + mt * 16 + g;
      const int col = bn + wn * 32 + nt * 8 + 2 * t;
      if (MODE == 0) {
        *(float2*)(Cf + (size_t)row * N + col) =
            make_float2(acc[mt][nt][0], acc[mt][nt][1]);
        *(float2*)(Cf + (size_t)(row + 8) * N + col) =
            make_float2(acc[mt][nt][2], acc[mt][nt][3]);
      } else {
        *(uint32_t*)(Ch + (size_t)row * N + col) =
            pack_h2(acc[mt][nt][0], acc[mt][nt][1]);
        *(uint32_t*)(Ch + (size_t)(row + 8) * N + col) =
            pack_h2(acc[mt][nt][2], acc[mt][nt][3]);
      }
    }
  }
}

// ---------------------------------------------------------------------------
// fp16 causal flash attention, 128-query CTA (2 m16 tiles per warp).
// S = Qh*Kh^T ; O += Ph*Vh.  K frags shared across tiles; V frags shared
// across both P tiles.  SMEM: Qh 16K | Kh x2 16K | Vh x2 16K = 48KB.
// ---------------------------------------------------------------------------
#define TQ 128
#define AQH 0
#define AKH 16384
#define AVH 32768
#define ASMEM_TOTAL 49152

__global__ __launch_bounds__(128) void attn1(
    const __half* __restrict__ qh, __half* __restrict__ oh) {
  extern __shared__ char sm[];
  const int qi = blockIdx.x, h = blockIdx.y, b = blockIdx.z;
  const int tid = threadIdx.x, w = tid >> 5, lane = tid & 31;
  const int g = lane >> 2, t = lane & 3;
  const int q0 = qi * TQ;
  const size_t rowQ = (size_t)(b * TT + q0);

  auto fillKV = [&](int kb, int bf) {
    const size_t base = (size_t)(b * TT + kb * 64) * 3 * CM + CM + h * 64;
    char* kh = sm + AKH + bf * 8192;
    char* vh = sm + AVH + bf * 8192;
#pragma unroll
    for (int i = tid; i < 512; i += 128) {
      int row = i >> 3, c = i & 7;
      uint32_t swo = sw128((uint32_t)(row * 128 + c * 16));
      size_t src = base + (size_t)row * 3 * CM + c * 8;
      cp16(smem_u32(kh + swo), qh + src);
      cp16(smem_u32(vh + swo), qh + src + CM);
    }
  };

  // prologue: Qh (128 rows) + KV block 0
#pragma unroll
  for (int i = tid; i < 1024; i += 128) {
    int row = i >> 3, c = i & 7;
    uint32_t swo = sw128((uint32_t)(row * 128 + c * 16));
    size_t src = (rowQ + row) * 3 * CM + h * 64 + c * 8;
    cp16(smem_u32(sm + AQH + swo), qh + src);
  }
  fillKV(0, 0);
  CP_COMMIT();

  float m[4] = {-1e30f, -1e30f, -1e30f, -1e30f};   // [tile*2 + rowhalf]
  float l[4] = {0.f, 0.f, 0.f, 0.f};
  float o[2][8][4];
#pragma unroll
  for (int T = 0; T < 2; T++)
#pragma unroll
    for (int j = 0; j < 8; j++)
#pragma unroll
      for (int r = 0; r < 4; r++) o[T][j][r] = 0.f;

  const uint32_t xg = (uint32_t)g << 4;
  const int KJ = 2 * qi + 2;                 // key blocks 0 .. 2qi+1

  for (int kj = 0; kj < KJ; kj++) {
    const int buf = kj & 1;
    if (kj + 1 < KJ) fillKV(kj + 1, buf ^ 1);
    CP_COMMIT();
    CP_WAIT(1);
    __syncthreads();

    const char* Kh = sm + AKH + buf * 8192;
    const char* Qh = sm + AQH;
    const uint32_t vhU = smem_u32(sm + AVH + buf * 8192);

    // ---- S = Qh Kh^T for both tiles (K frags loaded once per kt) ----
    float s[2][8][4];
#pragma unroll
    for (int T = 0; T < 2; T++)
#pragma unroll
      for (int j = 0; j < 8; j++)
#pragma unroll
        for (int r = 0; r < 4; r++) s[T][j][r] = 0.f;

#pragma unroll
    for (int kt = 0; kt < 4; kt++) {
      const uint32_t xo = ((uint32_t)(kt * 32 + t * 4)) ^ xg;
      const char* q0p = Qh + (w * 32 + g) * 128;
      const char* q1p = q0p + 16 * 128;
      uint32_t a00 = ldu(q0p + xo),        a01 = ldu(q0p + 1024 + xo);
      uint32_t a02 = ldu(q0p + (xo ^ 16)), a03 = ldu(q0p + 1024 + (xo ^ 16));
      uint32_t a10 = ldu(q1p + xo),        a11 = ldu(q1p + 1024 + xo);
      uint32_t a12 = ldu(q1p + (xo ^ 16)), a13 = ldu(q1p + 1024 + (xo ^ 16));
#pragma unroll
      for (int j = 0; j < 8; j++) {
        const char* krh = Kh + (j * 8 + g) * 128;
        uint32_t bh0 = ldu(krh + xo), bh1 = ldu(krh + (xo ^ 16));
        mma16(s[0][j], a00, a01, a02, a03, bh0, bh1);
        mma16(s[1][j], a10, a11, a12, a13, bh0, bh1);
      }
    }

    // scale 1/sqrt(64) + causal mask (global-index compare; only near diag)
#pragma unroll
    for (int T = 0; T < 2; T++)
#pragma unroll
      for (int j = 0; j < 8; j++)
#pragma unroll
        for (int r = 0; r < 4; r++) s[T][j][r] *= 0.125f;

    if (kj >= 2 * qi) {
      const int colb = kj * 64;
#pragma unroll
      for (int T = 0; T < 2; T++) {
        const int rg = q0 + w * 32 + T * 16 + g;
#pragma unroll
        for (int j = 0; j < 8; j++) {
          const int c = colb + j * 8 + 2 * t;
          if (c     > rg)     s[T][j][0] = -1e30f;
          if (c + 1 > rg)     s[T][j][1] = -1e30f;
          if (c     > rg + 8) s[T][j][2] = -1e30f;
          if (c + 1 > rg + 8) s[T][j][3] = -1e30f;
        }
      }
    }

    // ---- online softmax per tile ----
    uint32_t ph01[2][8], ph23[2][8];
#pragma unroll
    for (int T = 0; T < 2; T++) {
      float rm0 = -1e30f, rm1 = -1e30f;
#pragma unroll
      for (int j = 0; j < 8; j++) {
        rm0 = fmaxf(rm0, fmaxf(s[T][j][0], s[T][j][1]));
        rm1 = fmaxf(rm1, fmaxf(s[T][j][2], s[T][j][3]));
      }
      rm0 = fmaxf(rm0, __shfl_xor_sync(0xffffffffu, rm0, 1));
      rm0 = fmaxf(rm0, __shfl_xor_sync(0xffffffffu, rm0, 2));
      rm1 = fmaxf(rm1, __shfl_xor_sync(0xffffffffu, rm1, 1));
      rm1 = fmaxf(rm1, __shfl_xor_sync(0xffffffffu, rm1, 2));
      const float mn0 = fmaxf(m[2*T],   rm0);
      const float mn1 = fmaxf(m[2*T+1], rm1);
      const float al0 = __expf(m[2*T]   - mn0);
      const float al1 = __expf(m[2*T+1] - mn1);
      float rs0 = 0.f, rs1 = 0.f;
#pragma unroll
      for (int j = 0; j < 8; j++) {
        s[T][j][0] = __expf(s[T][j][0] - mn0);
        s[T][j][1] = __expf(s[T][j][1] - mn0);
        s[T][j][2] = __expf(s[T][j][2] - mn1);
        s[T][j][3] = __expf(s[T][j][3] - mn1);
        rs0 += s[T][j][0] + s[T][j][1];
        rs1 += s[T][j][2] + s[T][j][3];
      }
      rs0 += __shfl_xor_sync(0xffffffffu, rs0, 1);
      rs0 += __shfl_xor_sync(0xffffffffu, rs0, 2);
      rs1 += __shfl_xor_sync(0xffffffffu, rs1, 1);
      rs1 += __shfl_xor_sync(0xffffffffu, rs1, 2);
      l[2*T]   = l[2*T]   * al0 + rs0;  m[2*T]   = mn0;
      l[2*T+1] = l[2*T+1] * al1 + rs1;  m[2*T+1] = mn1;
#pragma unroll
      for (int j = 0; j < 8; j++) {
        o[T][j][0] *= al0; o[T][j][1] *= al0;
        o[T][j][2] *= al1; o[T][j][3] *= al1;
        ph01[T][j] = pack_h2(s[T][j][0], s[T][j][1]);
        ph23[T][j] = pack_h2(s[T][j][2], s[T][j][3]);
      }
    }

    // ---- O += Ph Vh (V frags loaded once, used by both tiles) ----
    const int qq = lane >> 3, rr = lane & 7;
#pragma unroll
    for (int kt = 0; kt < 4; kt++) {
      const uint32_t p00 = ph01[0][2*kt],   p01 = ph23[0][2*kt];
      const uint32_t p02 = ph01[0][2*kt+1], p03 = ph23[0][2*kt+1];
      const uint32_t p10 = ph01[1][2*kt],   p11 = ph23[1][2*kt];
      const uint32_t p12 = ph01[1][2*kt+1], p13 = ph23[1][2*kt+1];
      const uint32_t vrow = (uint32_t)(kt * 16 + ((qq & 1) << 3) + rr);
#pragma unroll
      for (int jp = 0; jp < 4; jp++) {
        const uint32_t off = sw128(vrow * 128 + (uint32_t)(jp * 32 + ((qq >> 1) << 4)));
        uint32_t vh0, vh1, vh2, vh3;
        ldsm4t(vh0, vh1, vh2, vh3, vhU + off);
        mma16(o[0][2*jp],     p00, p01, p02, p03, vh0, vh1);
        mma16(o[0][2*jp + 1], p00, p01, p02, p03, vh2, vh3);
        mma16(o[1][2*jp],     p10, p11, p12, p13, vh0, vh1);
        mma16(o[1][2*jp + 1], p10, p11, p12, p13, vh2, vh3);
      }
    }
    __syncthreads();   // tiles consumed before next prefetch overwrites
  }

  // ---- epilogue: O /= l, fp16 ----
#pragma unroll
  for (int T = 0; T < 2; T++) {
    const float i0 = 1.f / l[2*T], i1 = 1.f / l[2*T+1];
    const size_t ro0 = (rowQ + w * 32 + T * 16 + g) * CM + h * 64;
    const size_t ro1 = ro0 + 8 * (size_t)CM;
#pragma unroll
    for (int j = 0; j < 8; j++) {
      const int col = j * 8 + 2 * t;
      *(uint32_t*)(oh + ro0 + col) = pack_h2(o[T][j][0] * i0, o[T][j][1] * i0);
      *(uint32_t*)(oh + ro1 + col) = pack_h2(o[T][j][2] * i1, o[T][j][3] * i1);
    }
  }
}

// ---------------------------------------------------------------------------
extern "C" void kernel_launch(void* const* d_in, const int* in_sizes, int n_in,
                              void* d_out, int out_size) {
  const float* x     = (const float*)d_in[0];   // [4,2048,1024]
  const float* w_qkv = (const float*)d_in[1];   // [3072,1024]
  const float* w_out = (const float*)d_in[2];   // [1024,1024]
  float* out = (float*)d_out;

  __half *xh, *wqh, *woh, *qkvh, *ath;
  cudaGetSymbolAddress((void**)&xh,  g_x_hi);
  cudaGetSymbolAddress((void**)&wqh, g_wqkv_hi);
  cudaGetSymbolAddress((void**)&woh, g_wout_hi);
  cudaGetSymbolAddress((void**)&qkvh, g_qkv_hi);
  cudaGetSymbolAddress((void**)&ath, g_att_hi);

  cudaFuncSetAttribute(gemmH<1>, cudaFuncAttributeMaxDynamicSharedMemorySize, GSMEM_TOTAL);
  cudaFuncSetAttribute(gemmH<0>, cudaFuncAttributeMaxDynamicSharedMemorySize, GSMEM_TOTAL);
  cudaFuncSetAttribute(attn1,    cudaFuncAttributeMaxDynamicSharedMemorySize, ASMEM_TOTAL);

  // 0) cast all inputs to fp16 (single launch)
  cast_all<<<(NX + NW + NO + 255) / 256, 256>>>(x, w_qkv, w_out, xh, wqh, woh);

  // 1) QKV projection -> qkv fp16 (1-pass)
  gemmH<1><<<dim3(3*CM/128, MR/128), 256, GSMEM_TOTAL>>>(
      xh, wqh, nullptr, qkvh, 3*CM, CM);

  // 2) causal flash attention -> att fp16 (128-query CTAs)
  attn1<<<dim3(TT/TQ, HH, BB), 128, ASMEM_TOTAL>>>(qkvh, ath);

  // 3) output projection -> fp32 out (1-pass)
  gemmH<0><<<dim3(CM/128, MR/128), 256, GSMEM_TOTAL>>>(
      ath, woh, out, nullptr, CM, CM);
}